// round 1
// baseline (speedup 1.0000x reference)
#include <cuda_runtime.h>
#include <math.h>

#define N_NODES   20000
#define N_EDGES   640000
#define IN_CH     64
#define EDGE_DIM  16
#define HID       128
#define NLAYERS   3
#define NGRAPHS   128

// ---------------- scratch (device globals: no allocation allowed) ----------------
__device__ float     g_h[2][N_NODES * HID];     // ping-pong node features
__device__ float     g_aggr[N_NODES * HID];     // per-layer scatter-add target
__device__ float     g_mean[NGRAPHS * HID];
__device__ unsigned  g_maxe[NGRAPHS * HID];     // monotonic-encoded float max
__device__ float     g_cnt[NGRAPHS];

// monotonic float<->uint encoding for atomicMax on floats (handles negatives)
__device__ __forceinline__ unsigned fenc(float f) {
    unsigned u = __float_as_uint(f);
    return (u & 0x80000000u) ? ~u : (u | 0x80000000u);
}
__device__ __forceinline__ float fdec(unsigned u) {
    return (u & 0x80000000u) ? __uint_as_float(u & 0x7FFFFFFFu)
                             : __uint_as_float(~u);
}
#define ENC_NEG_INF 0x007FFFFFu   // fenc(-inf)

// ---------------- node projection: h0 = x @ W + b  ([20000,64]@[64,128]) ----------
__global__ void node_proj_kernel(const float* __restrict__ x,
                                 const float* __restrict__ W,
                                 const float* __restrict__ B) {
    __shared__ float sX[16][IN_CH];
    const int t  = threadIdx.x;            // 256 threads
    const int n0 = blockIdx.x * 16;
    for (int i = t; i < 16 * IN_CH; i += 256) {
        int r = i >> 6, c = i & 63;
        sX[r][c] = x[(size_t)(n0 + r) * IN_CH + c];
    }
    __syncthreads();
    const int row = t >> 4;
    const int col = (t & 15) * 8;
    float acc[8];
    {
        float4 b0 = *reinterpret_cast<const float4*>(B + col);
        float4 b1 = *reinterpret_cast<const float4*>(B + col + 4);
        acc[0]=b0.x; acc[1]=b0.y; acc[2]=b0.z; acc[3]=b0.w;
        acc[4]=b1.x; acc[5]=b1.y; acc[6]=b1.z; acc[7]=b1.w;
    }
    #pragma unroll 8
    for (int k = 0; k < IN_CH; k++) {
        float a = sX[row][k];
        float4 w0 = *reinterpret_cast<const float4*>(W + (size_t)k * HID + col);
        float4 w1 = *reinterpret_cast<const float4*>(W + (size_t)k * HID + col + 4);
        acc[0] = fmaf(a, w0.x, acc[0]); acc[1] = fmaf(a, w0.y, acc[1]);
        acc[2] = fmaf(a, w0.z, acc[2]); acc[3] = fmaf(a, w0.w, acc[3]);
        acc[4] = fmaf(a, w1.x, acc[4]); acc[5] = fmaf(a, w1.y, acc[5]);
        acc[6] = fmaf(a, w1.z, acc[6]); acc[7] = fmaf(a, w1.w, acc[7]);
    }
    float* out = g_h[0] + (size_t)(n0 + row) * HID + col;
    *reinterpret_cast<float4*>(out)     = make_float4(acc[0], acc[1], acc[2], acc[3]);
    *reinterpret_cast<float4*>(out + 4) = make_float4(acc[4], acc[5], acc[6], acc[7]);
}

// ---------------- zero aggr ----------------
__global__ void zero_aggr_kernel() {
    g_aggr[blockIdx.x * 256 + threadIdx.x] = 0.f;
}

// ---------------- fused edge message MLP + scatter-add ----------------
// Per 128-edge tile:
//   A = [h[src] , edge_attr]  (gathered)            [128 x 144]
//   Hd = relu(A @ W1 + b1)  -> SMEM                 [128 x 128]
//   M  = Hd @ W2 + b2                               [128 x 128]
//   atomicAdd into g_aggr[dst]
#define SMEM_MSG_WORDS (128*17 + 16*128 + 128*132 + 256)
#define SMEM_MSG_BYTES (SMEM_MSG_WORDS * 4)

__global__ void __launch_bounds__(256, 2) msg_kernel(
    int ping,
    const float* __restrict__ eattr,
    const int*   __restrict__ srcIdx,
    const int*   __restrict__ dstIdx,
    const float* __restrict__ W1, const float* __restrict__ B1,
    const float* __restrict__ W2, const float* __restrict__ B2)
{
    extern __shared__ float sm[];
    float (*sA)[17]  = (float(*)[17]) sm;                               // 128x17
    float (*sB)[128] = (float(*)[128])(sm + 128*17);                    // 16x128
    float (*sH)[132] = (float(*)[132])(sm + 128*17 + 16*128);           // 128x132
    int*   sDst      = (int*)(sm + 128*17 + 16*128 + 128*132);          // 128
    int*   sSrc      = sDst + 128;                                      // 128

    const float* __restrict__ h = g_h[ping];
    const int t  = threadIdx.x;
    const int tx = t & 15;
    const int ty = t >> 4;
    const int e0 = blockIdx.x * 128;

    if (t < 128) { sSrc[t] = srcIdx[e0 + t]; sDst[t] = dstIdx[e0 + t]; }

    float acc[8][8];
    #pragma unroll
    for (int i = 0; i < 8; i++)
        #pragma unroll
        for (int j = 0; j < 8; j++) acc[i][j] = 0.f;

    // -------- stage A: hidden = relu(A @ W1 + b1), K = 144 = 9 tiles of 16 ----
    for (int kt = 0; kt < 9; kt++) {
        const int k0 = kt * 16;
        __syncthreads();
        #pragma unroll
        for (int q = 0; q < 2; q++) {             // gather A tile (128x16)
            int s = t * 2 + q;
            int r = s >> 2;
            int c = (s & 3) * 4;
            float4 v;
            if (kt < 8)
                v = *reinterpret_cast<const float4*>(h + (size_t)sSrc[r] * HID + k0 + c);
            else
                v = *reinterpret_cast<const float4*>(eattr + (size_t)(e0 + r) * EDGE_DIM + c);
            sA[r][c] = v.x; sA[r][c+1] = v.y; sA[r][c+2] = v.z; sA[r][c+3] = v.w;
        }
        #pragma unroll
        for (int q = 0; q < 2; q++) {             // W1 tile (16x128)
            int s  = t * 2 + q;
            int kr = s >> 5;
            int c  = (s & 31) * 4;
            *reinterpret_cast<float4*>(&sB[kr][c]) =
                *reinterpret_cast<const float4*>(W1 + (size_t)(k0 + kr) * HID + c);
        }
        __syncthreads();
        #pragma unroll
        for (int k = 0; k < 16; k++) {
            float a[8];
            #pragma unroll
            for (int i = 0; i < 8; i++) a[i] = sA[ty*8 + i][k];
            float4 b0 = *reinterpret_cast<float4*>(&sB[k][tx*8]);
            float4 b1 = *reinterpret_cast<float4*>(&sB[k][tx*8 + 4]);
            float bb[8] = {b0.x, b0.y, b0.z, b0.w, b1.x, b1.y, b1.z, b1.w};
            #pragma unroll
            for (int i = 0; i < 8; i++)
                #pragma unroll
                for (int j = 0; j < 8; j++)
                    acc[i][j] = fmaf(a[i], bb[j], acc[i][j]);
        }
    }

    // bias + relu -> sH ; reset acc for stage B
    {
        float4 b0 = *reinterpret_cast<const float4*>(B1 + tx*8);
        float4 b1 = *reinterpret_cast<const float4*>(B1 + tx*8 + 4);
        float bb[8] = {b0.x, b0.y, b0.z, b0.w, b1.x, b1.y, b1.z, b1.w};
        __syncthreads();
        #pragma unroll
        for (int i = 0; i < 8; i++)
            #pragma unroll
            for (int j = 0; j < 8; j++) {
                sH[ty*8 + i][tx*8 + j] = fmaxf(acc[i][j] + bb[j], 0.f);
                acc[i][j] = 0.f;
            }
    }

    // -------- stage B: M = hidden @ W2 + b2, K = 128 = 8 tiles of 16 ----------
    for (int kt = 0; kt < 8; kt++) {
        const int k0 = kt * 16;
        __syncthreads();
        #pragma unroll
        for (int q = 0; q < 2; q++) {             // W2 tile (16x128)
            int s  = t * 2 + q;
            int kr = s >> 5;
            int c  = (s & 31) * 4;
            *reinterpret_cast<float4*>(&sB[kr][c]) =
                *reinterpret_cast<const float4*>(W2 + (size_t)(k0 + kr) * HID + c);
        }
        __syncthreads();
        #pragma unroll
        for (int k = 0; k < 16; k++) {
            float a[8];
            #pragma unroll
            for (int i = 0; i < 8; i++) a[i] = sH[ty*8 + i][k0 + k];
            float4 b0 = *reinterpret_cast<float4*>(&sB[k][tx*8]);
            float4 b1 = *reinterpret_cast<float4*>(&sB[k][tx*8 + 4]);
            float bb[8] = {b0.x, b0.y, b0.z, b0.w, b1.x, b1.y, b1.z, b1.w};
            #pragma unroll
            for (int i = 0; i < 8; i++)
                #pragma unroll
                for (int j = 0; j < 8; j++)
                    acc[i][j] = fmaf(a[i], bb[j], acc[i][j]);
        }
    }

    // m + b2 -> sH, then coalesced scatter-add
    {
        float4 c0 = *reinterpret_cast<const float4*>(B2 + tx*8);
        float4 c1 = *reinterpret_cast<const float4*>(B2 + tx*8 + 4);
        float bb[8] = {c0.x, c0.y, c0.z, c0.w, c1.x, c1.y, c1.z, c1.w};
        __syncthreads();
        #pragma unroll
        for (int i = 0; i < 8; i++)
            #pragma unroll
            for (int j = 0; j < 8; j++)
                sH[ty*8 + i][tx*8 + j] = acc[i][j] + bb[j];
    }
    __syncthreads();
    #pragma unroll 4
    for (int it = 0; it < 64; it++) {
        int idx = it * 256 + t;
        int r = idx >> 7, c = idx & 127;
        atomicAdd(&g_aggr[(size_t)sDst[r] * HID + c], sH[r][c]);
    }
}

// ---------------- update: u = relu([h,aggr]@W+b); LN; h' = relu(LN)+h ----------
__global__ void update_kernel(int ping,
                              const float* __restrict__ W,
                              const float* __restrict__ B,
                              const float* __restrict__ LG,
                              const float* __restrict__ LB)
{
    __shared__ float sIn[16][256];
    __shared__ float sS[16][16], sQ[16][16];
    __shared__ float sMu[16], sRs[16];
    const float* __restrict__ h    = g_h[ping];
    float*       __restrict__ hout = g_h[ping ^ 1];
    const int t  = threadIdx.x;
    const int n0 = blockIdx.x * 16;

    for (int i = t; i < 16 * 128; i += 256) {
        int r = i >> 7, c = i & 127;
        sIn[r][c]       = h[(size_t)(n0 + r) * HID + c];
        sIn[r][128 + c] = g_aggr[(size_t)(n0 + r) * HID + c];
    }
    __syncthreads();

    const int row = t >> 4;
    const int cg  = t & 15;
    const int col = cg * 8;
    float acc[8];
    {
        float4 b0 = *reinterpret_cast<const float4*>(B + col);
        float4 b1 = *reinterpret_cast<const float4*>(B + col + 4);
        acc[0]=b0.x; acc[1]=b0.y; acc[2]=b0.z; acc[3]=b0.w;
        acc[4]=b1.x; acc[5]=b1.y; acc[6]=b1.z; acc[7]=b1.w;
    }
    #pragma unroll 8
    for (int k = 0; k < 256; k++) {
        float a = sIn[row][k];
        float4 w0 = *reinterpret_cast<const float4*>(W + (size_t)k * HID + col);
        float4 w1 = *reinterpret_cast<const float4*>(W + (size_t)k * HID + col + 4);
        acc[0] = fmaf(a, w0.x, acc[0]); acc[1] = fmaf(a, w0.y, acc[1]);
        acc[2] = fmaf(a, w0.z, acc[2]); acc[3] = fmaf(a, w0.w, acc[3]);
        acc[4] = fmaf(a, w1.x, acc[4]); acc[5] = fmaf(a, w1.y, acc[5]);
        acc[6] = fmaf(a, w1.z, acc[6]); acc[7] = fmaf(a, w1.w, acc[7]);
    }
    float s = 0.f, q = 0.f;
    #pragma unroll
    for (int j = 0; j < 8; j++) {
        acc[j] = fmaxf(acc[j], 0.f);
        s += acc[j]; q += acc[j] * acc[j];
    }
    sS[row][cg] = s; sQ[row][cg] = q;
    __syncthreads();
    if (t < 16) {
        float S = 0.f, Q = 0.f;
        #pragma unroll
        for (int i = 0; i < 16; i++) { S += sS[t][i]; Q += sQ[t][i]; }
        float mu  = S * (1.f / 128.f);
        float var = Q * (1.f / 128.f) - mu * mu;
        sMu[t] = mu;
        sRs[t] = rsqrtf(var + 1e-5f);
    }
    __syncthreads();
    const float mu = sMu[row], rs = sRs[row];
    float o[8];
    #pragma unroll
    for (int j = 0; j < 8; j++) {
        float v = (acc[j] - mu) * rs * LG[col + j] + LB[col + j];
        o[j] = fmaxf(v, 0.f) + sIn[row][col + j];
    }
    float* op = hout + (size_t)(n0 + row) * HID + col;
    *reinterpret_cast<float4*>(op)     = make_float4(o[0], o[1], o[2], o[3]);
    *reinterpret_cast<float4*>(op + 4) = make_float4(o[4], o[5], o[6], o[7]);
}

// ---------------- pooling ----------------
__global__ void pool_init_kernel() {
    int i = blockIdx.x * 256 + threadIdx.x;   // 64 blocks x 256 = 16384
    g_mean[i] = 0.f;
    g_maxe[i] = ENC_NEG_INF;
    if (i < NGRAPHS) g_cnt[i] = 0.f;
}

__global__ void pool_acc_kernel(int ping, const int* __restrict__ batch) {
    int idx = blockIdx.x * 256 + threadIdx.x; // 10000 blocks
    int n = idx >> 7, c = idx & 127;
    float v = g_h[ping][idx];
    int gph = batch[n];
    atomicAdd(&g_mean[gph * HID + c], v);
    atomicMax(&g_maxe[gph * HID + c], fenc(v));
    if (c == 0) atomicAdd(&g_cnt[gph], 1.f);
}

// ---------------- readout FFN ----------------
__global__ void readout_kernel(const float* __restrict__ W1,
                               const float* __restrict__ B1,
                               const float* __restrict__ W2,
                               const float* __restrict__ B2,
                               float* __restrict__ out)
{
    __shared__ float gv[256];
    __shared__ float red[128];
    const int g = blockIdx.x, t = threadIdx.x;   // 128 threads
    float cnt = fmaxf(g_cnt[g], 1.f);
    gv[t]       = g_mean[g * HID + t] / cnt;
    gv[128 + t] = fdec(g_maxe[g * HID + t]);
    __syncthreads();
    float a = B1[t];
    #pragma unroll 8
    for (int k = 0; k < 256; k++)
        a = fmaf(gv[k], W1[(size_t)k * HID + t], a);
    a = fmaxf(a, 0.f) * W2[t];
    red[t] = a;
    __syncthreads();
    for (int s2 = 64; s2 > 0; s2 >>= 1) {
        if (t < s2) red[t] += red[t + s2];
        __syncthreads();
    }
    if (t == 0) out[g] = red[0] + B2[0];
}

// ---------------- launch ----------------
extern "C" void kernel_launch(void* const* d_in, const int* in_sizes, int n_in,
                              void* d_out, int out_size)
{
    const float* x     = (const float*)d_in[0];
    const int*   ei    = (const int*)  d_in[1];
    const float* eattr = (const float*)d_in[2];
    const int*   batch = (const int*)  d_in[3];
    const float* npw   = (const float*)d_in[4];
    const float* npb   = (const float*)d_in[5];
    const float* mw1   = (const float*)d_in[6];
    const float* mb1   = (const float*)d_in[7];
    const float* mw2   = (const float*)d_in[8];
    const float* mb2   = (const float*)d_in[9];
    const float* uw    = (const float*)d_in[10];
    const float* ub    = (const float*)d_in[11];
    const float* lg    = (const float*)d_in[12];
    const float* lb    = (const float*)d_in[13];
    const float* fw1   = (const float*)d_in[14];
    const float* fb1   = (const float*)d_in[15];
    const float* fw2   = (const float*)d_in[16];
    const float* fb2   = (const float*)d_in[17];
    float* out = (float*)d_out;

    const int* srcIdx = ei;            // edge_index[0]
    const int* dstIdx = ei + N_EDGES;  // edge_index[1]

    cudaFuncSetAttribute(msg_kernel,
                         cudaFuncAttributeMaxDynamicSharedMemorySize,
                         SMEM_MSG_BYTES);

    node_proj_kernel<<<N_NODES / 16, 256>>>(x, npw, npb);

    int ping = 0;
    for (int l = 0; l < NLAYERS; l++) {
        zero_aggr_kernel<<<(N_NODES * HID) / 256, 256>>>();
        msg_kernel<<<N_EDGES / 128, 256, SMEM_MSG_BYTES>>>(
            ping, eattr, srcIdx, dstIdx,
            mw1 + (size_t)l * (HID + EDGE_DIM) * HID, mb1 + (size_t)l * HID,
            mw2 + (size_t)l * HID * HID,              mb2 + (size_t)l * HID);
        update_kernel<<<N_NODES / 16, 256>>>(
            ping,
            uw + (size_t)l * 2 * HID * HID, ub + (size_t)l * HID,
            lg + (size_t)l * HID,           lb + (size_t)l * HID);
        ping ^= 1;
    }

    pool_init_kernel<<<(NGRAPHS * HID) / 256, 256>>>();
    pool_acc_kernel<<<(N_NODES * HID) / 256, 256>>>(ping, batch);
    readout_kernel<<<NGRAPHS, 128>>>(fw1, fb1, fw2, fb2, out);
}

// round 3
// speedup vs baseline: 2.0795x; 2.0795x over previous
#include <cuda_runtime.h>
#include <cuda_bf16.h>
#include <cstdint>
#include <math.h>

#define N_NODES   20000
#define N_EDGES   640000
#define IN_CH     64
#define EDGE_DIM  16
#define HID       128
#define NLAYERS   3
#define NGRAPHS   128
#define N_TILES   (N_EDGES / 128)   // 5000
#define MSG_GRID  152

// ================= scratch (device globals) =================
__device__ float     g_h[2][N_NODES * HID];
__device__ float     g_aggr[N_NODES * HID];
__device__ float     g_mean[NGRAPHS * HID];
__device__ unsigned  g_maxe[NGRAPHS * HID];
__device__ float     g_cnt[NGRAPHS];

__device__ __forceinline__ unsigned fenc(float f) {
    unsigned u = __float_as_uint(f);
    return (u & 0x80000000u) ? ~u : (u | 0x80000000u);
}
__device__ __forceinline__ float fdec(unsigned u) {
    return (u & 0x80000000u) ? __uint_as_float(u & 0x7FFFFFFFu)
                             : __uint_as_float(~u);
}
#define ENC_NEG_INF 0x007FFFFFu

// ---- bf16 hi/lo split of a float pair (even k in LOW half of word) ----
__device__ __forceinline__ void cvt_pair(float f0, float f1,
                                         uint32_t& hi, uint32_t& lo) {
    uint32_t u0 = __float_as_uint(f0), u1 = __float_as_uint(f1);
    hi = __byte_perm(u0, u1, 0x7632);                 // truncated bf16 pair
    float l0 = f0 - __uint_as_float(u0 & 0xffff0000u);
    float l1 = f1 - __uint_as_float(u1 & 0xffff0000u);
    asm("cvt.rn.bf16x2.f32 %0, %1, %2;" : "=r"(lo) : "f"(l1), "f"(l0));
}

// ---- warp mma m16n8k16 row.col f32.bf16.bf16.f32 (sm_80+, no 'a' target) ----
__device__ __forceinline__ void mma16816(float* d,
                                         uint32_t a0, uint32_t a1,
                                         uint32_t a2, uint32_t a3,
                                         uint32_t b0, uint32_t b1) {
    asm volatile(
        "mma.sync.aligned.m16n8k16.row.col.f32.bf16.bf16.f32 "
        "{%0,%1,%2,%3}, {%4,%5,%6,%7}, {%8,%9}, {%0,%1,%2,%3};"
        : "+f"(d[0]), "+f"(d[1]), "+f"(d[2]), "+f"(d[3])
        : "r"(a0), "r"(a1), "r"(a2), "r"(a3), "r"(b0), "r"(b1));
}

// ================= node projection =================
__global__ void node_proj_kernel(const float* __restrict__ x,
                                 const float* __restrict__ W,
                                 const float* __restrict__ B) {
    __shared__ float sX[16][IN_CH];
    const int t  = threadIdx.x;
    const int n0 = blockIdx.x * 16;
    for (int i = t; i < 16 * IN_CH; i += 256) {
        int r = i >> 6, c = i & 63;
        sX[r][c] = x[(size_t)(n0 + r) * IN_CH + c];
    }
    __syncthreads();
    const int row = t >> 4;
    const int col = (t & 15) * 8;
    float acc[8];
    {
        float4 b0 = *reinterpret_cast<const float4*>(B + col);
        float4 b1 = *reinterpret_cast<const float4*>(B + col + 4);
        acc[0]=b0.x; acc[1]=b0.y; acc[2]=b0.z; acc[3]=b0.w;
        acc[4]=b1.x; acc[5]=b1.y; acc[6]=b1.z; acc[7]=b1.w;
    }
    #pragma unroll 8
    for (int k = 0; k < IN_CH; k++) {
        float a = sX[row][k];
        float4 w0 = *reinterpret_cast<const float4*>(W + (size_t)k * HID + col);
        float4 w1 = *reinterpret_cast<const float4*>(W + (size_t)k * HID + col + 4);
        acc[0] = fmaf(a, w0.x, acc[0]); acc[1] = fmaf(a, w0.y, acc[1]);
        acc[2] = fmaf(a, w0.z, acc[2]); acc[3] = fmaf(a, w0.w, acc[3]);
        acc[4] = fmaf(a, w1.x, acc[4]); acc[5] = fmaf(a, w1.y, acc[5]);
        acc[6] = fmaf(a, w1.z, acc[6]); acc[7] = fmaf(a, w1.w, acc[7]);
    }
    float* out = g_h[0] + (size_t)(n0 + row) * HID + col;
    *reinterpret_cast<float4*>(out)     = make_float4(acc[0], acc[1], acc[2], acc[3]);
    *reinterpret_cast<float4*>(out + 4) = make_float4(acc[4], acc[5], acc[6], acc[7]);
}

__global__ void zero_aggr_kernel() {
    g_aggr[blockIdx.x * 256 + threadIdx.x] = 0.f;
}

// ================= fused tensor-core message kernel =================
// Persistent: weights pre-split bf16 hi/lo into SMEM in mma-fragment order.
// Per 128-edge tile:
//   A1 = split([h[src], eattr])  -> SMEM (row-major bf16, stride 76 words)
//   D1 = A1h@W1h + A1h@W1l + A1l@W1h   (mma.sync, fp32 acc)
//   A2 = split(relu(D1 + b1))    -> same SMEM tile (warp-local rows)
//   D2 = A2h@W2h + A2h@W2l + A2l@W2h
//   atomicAdd(g_aggr[dst], D2 + b2)  directly from fragments

#define A_STRIDE_W 76                 // words per row (152 bf16), conflict-free
// SMEM layout (bytes)
#define OFF_DST   0                   // int[128]
#define OFF_B1S   512                 // float[128]
#define OFF_B2S   1024                // float[128]
#define OFF_AH    1536                // 128*76*4 = 38912
#define OFF_AL    40448               // 38912
#define OFF_W1H   79360               // 9*16*32*2*4 = 36864
#define OFF_W1L   116224              // 36864
#define OFF_W2H   153088              // 8*16*32*2*4 = 32768
#define OFF_W2L   185856              // 32768
#define SMEM_MSG_BYTES 218624

__global__ void __launch_bounds__(256, 1) msg_tc_kernel(
    int ping,
    const float* __restrict__ eattr,
    const int*   __restrict__ srcIdx,
    const int*   __restrict__ dstIdx,
    const float* __restrict__ W1, const float* __restrict__ B1,
    const float* __restrict__ W2, const float* __restrict__ B2)
{
    extern __shared__ char smem[];
    int*      sDst = (int*)     (smem + OFF_DST);
    float*    b1s  = (float*)   (smem + OFF_B1S);
    float*    b2s  = (float*)   (smem + OFF_B2S);
    uint32_t* aH   = (uint32_t*)(smem + OFF_AH);
    uint32_t* aL   = (uint32_t*)(smem + OFF_AL);
    uint32_t* w1H  = (uint32_t*)(smem + OFF_W1H);
    uint32_t* w1L  = (uint32_t*)(smem + OFF_W1L);
    uint32_t* w2H  = (uint32_t*)(smem + OFF_W2H);
    uint32_t* w2L  = (uint32_t*)(smem + OFF_W2L);

    const float* __restrict__ h = g_h[ping];
    const int t    = threadIdx.x;
    const int lane = t & 31;
    const int warp = t >> 5;

    // ---- stage W1/W2 as hi/lo bf16 fragments (once per CTA) ----
    // word idx = ((kt*16 + nt)*32 + lane)*2 + r ; packs (k0, k0+1) for
    // k0 = kt*16 + (lane%4)*2 + r*8, n = nt*8 + lane/4
    for (int w = t; w < 9 * 16 * 32 * 2; w += 256) {
        int r = w & 1, idx = w >> 1;
        int l = idx & 31, tile = idx >> 5;
        int nt = tile & 15, kt = tile >> 4;
        int n  = nt * 8 + (l >> 2);
        int k0 = kt * 16 + (l & 3) * 2 + r * 8;
        float f0 = W1[(size_t)k0 * HID + n];
        float f1 = W1[(size_t)(k0 + 1) * HID + n];
        cvt_pair(f0, f1, w1H[w], w1L[w]);
    }
    for (int w = t; w < 8 * 16 * 32 * 2; w += 256) {
        int r = w & 1, idx = w >> 1;
        int l = idx & 31, tile = idx >> 5;
        int nt = tile & 15, kt = tile >> 4;
        int n  = nt * 8 + (l >> 2);
        int k0 = kt * 16 + (l & 3) * 2 + r * 8;
        float f0 = W2[(size_t)k0 * HID + n];
        float f1 = W2[(size_t)(k0 + 1) * HID + n];
        cvt_pair(f0, f1, w2H[w], w2L[w]);
    }
    if (t < HID) { b1s[t] = B1[t]; b2s[t] = B2[t]; }
    __syncthreads();

    const int m0 = warp * 16 + (lane >> 2);   // fragment row (and m0+8)
    float acc[16][4];

    for (int tile = blockIdx.x; tile < N_TILES; tile += gridDim.x) {
        const int e0 = tile * 128;

        __syncthreads();   // previous iter fully consumed (sDst, A)

        // ---- gather + split: A1 = [h[src], eattr] (hi/lo) ----
        {
            const int row = t & 127;
            const int hf  = t >> 7;                 // 0: k0..63, 1: k64..127(+eattr)
            const int src = srcIdx[e0 + row];
            if (hf == 0) sDst[row] = dstIdx[e0 + row];
            const float4* hp = reinterpret_cast<const float4*>(
                h + (size_t)src * HID) + hf * 16;
            uint32_t* dstH = aH + row * A_STRIDE_W + hf * 32;
            uint32_t* dstL = aL + row * A_STRIDE_W + hf * 32;
            #pragma unroll
            for (int q = 0; q < 16; q++) {
                float4 v = hp[q];
                uint32_t h0, l0, h1, l1;
                cvt_pair(v.x, v.y, h0, l0);
                cvt_pair(v.z, v.w, h1, l1);
                dstH[q*2] = h0; dstH[q*2+1] = h1;
                dstL[q*2] = l0; dstL[q*2+1] = l1;
            }
            if (hf == 1) {                          // edge_attr -> words 64..71
                const float4* ep = reinterpret_cast<const float4*>(
                    eattr + (size_t)(e0 + row) * EDGE_DIM);
                #pragma unroll
                for (int q = 0; q < 4; q++) {
                    float4 v = ep[q];
                    uint32_t h0, l0, h1, l1;
                    cvt_pair(v.x, v.y, h0, l0);
                    cvt_pair(v.z, v.w, h1, l1);
                    aH[row * A_STRIDE_W + 64 + q*2]     = h0;
                    aH[row * A_STRIDE_W + 64 + q*2 + 1] = h1;
                    aL[row * A_STRIDE_W + 64 + q*2]     = l0;
                    aL[row * A_STRIDE_W + 64 + q*2 + 1] = l1;
                }
            }
        }
        __syncthreads();

        // ---- GEMM1: K = 144 (9 ktiles), 3-term split ----
        #pragma unroll
        for (int nt = 0; nt < 16; nt++)
            #pragma unroll
            for (int c = 0; c < 4; c++) acc[nt][c] = 0.f;

        #pragma unroll
        for (int kt = 0; kt < 9; kt++) {
            const int base = m0 * A_STRIDE_W + kt * 8 + (lane & 3);
            uint32_t ah0 = aH[base],               ah1 = aH[base + 8 * A_STRIDE_W];
            uint32_t ah2 = aH[base + 4],           ah3 = aH[base + 8 * A_STRIDE_W + 4];
            uint32_t al0 = aL[base],               al1 = aL[base + 8 * A_STRIDE_W];
            uint32_t al2 = aL[base + 4],           al3 = aL[base + 8 * A_STRIDE_W + 4];
            #pragma unroll
            for (int nt = 0; nt < 16; nt++) {
                int bw = ((kt * 16 + nt) * 32 + lane) * 2;
                uint2 bh = *reinterpret_cast<uint2*>(&w1H[bw]);
                uint2 bl = *reinterpret_cast<uint2*>(&w1L[bw]);
                mma16816(acc[nt], ah0, ah1, ah2, ah3, bh.x, bh.y);
                mma16816(acc[nt], ah0, ah1, ah2, ah3, bl.x, bl.y);
                mma16816(acc[nt], al0, al1, al2, al3, bh.x, bh.y);
            }
        }

        // ---- epi1: relu(D1+b1) -> split -> A2 (warp-local rows) ----
        #pragma unroll
        for (int nt = 0; nt < 16; nt++) {
            int n = nt * 8 + (lane & 3) * 2;
            float b0 = b1s[n], b1v = b1s[n + 1];
            float f0 = fmaxf(acc[nt][0] + b0, 0.f);
            float f1 = fmaxf(acc[nt][1] + b1v, 0.f);
            float f2 = fmaxf(acc[nt][2] + b0, 0.f);
            float f3 = fmaxf(acc[nt][3] + b1v, 0.f);
            uint32_t h0, l0, h1, l1;
            cvt_pair(f0, f1, h0, l0);
            cvt_pair(f2, f3, h1, l1);
            int wa = m0 * A_STRIDE_W + n / 2;
            int wb = (m0 + 8) * A_STRIDE_W + n / 2;
            aH[wa] = h0; aL[wa] = l0;
            aH[wb] = h1; aL[wb] = l1;
        }
        __syncwarp();

        // ---- GEMM2: K = 128 (8 ktiles) ----
        #pragma unroll
        for (int nt = 0; nt < 16; nt++)
            #pragma unroll
            for (int c = 0; c < 4; c++) acc[nt][c] = 0.f;

        #pragma unroll
        for (int kt = 0; kt < 8; kt++) {
            const int base = m0 * A_STRIDE_W + kt * 8 + (lane & 3);
            uint32_t ah0 = aH[base],               ah1 = aH[base + 8 * A_STRIDE_W];
            uint32_t ah2 = aH[base + 4],           ah3 = aH[base + 8 * A_STRIDE_W + 4];
            uint32_t al0 = aL[base],               al1 = aL[base + 8 * A_STRIDE_W];
            uint32_t al2 = aL[base + 4],           al3 = aL[base + 8 * A_STRIDE_W + 4];
            #pragma unroll
            for (int nt = 0; nt < 16; nt++) {
                int bw = ((kt * 16 + nt) * 32 + lane) * 2;
                uint2 bh = *reinterpret_cast<uint2*>(&w2H[bw]);
                uint2 bl = *reinterpret_cast<uint2*>(&w2L[bw]);
                mma16816(acc[nt], ah0, ah1, ah2, ah3, bh.x, bh.y);
                mma16816(acc[nt], ah0, ah1, ah2, ah3, bl.x, bl.y);
                mma16816(acc[nt], al0, al1, al2, al3, bh.x, bh.y);
            }
        }

        // ---- epi2: scatter-add D2 + b2 from fragments ----
        {
            const int d0 = sDst[m0];
            const int d1 = sDst[m0 + 8];
            float* r0 = g_aggr + (size_t)d0 * HID;
            float* r1 = g_aggr + (size_t)d1 * HID;
            #pragma unroll
            for (int nt = 0; nt < 16; nt++) {
                int n = nt * 8 + (lane & 3) * 2;
                float b0 = b2s[n], b1v = b2s[n + 1];
                atomicAdd(r0 + n,     acc[nt][0] + b0);
                atomicAdd(r0 + n + 1, acc[nt][1] + b1v);
                atomicAdd(r1 + n,     acc[nt][2] + b0);
                atomicAdd(r1 + n + 1, acc[nt][3] + b1v);
            }
        }
    }
}

// ================= update: 128x128x256 tiled SGEMM + LN =================
__global__ void __launch_bounds__(256, 1) update_kernel(
    int ping,
    const float* __restrict__ W,
    const float* __restrict__ B,
    const float* __restrict__ LG,
    const float* __restrict__ LB)
{
    __shared__ float sA[128][17];
    __shared__ float sB[16][128];
    const float* __restrict__ h    = g_h[ping];
    float*       __restrict__ hout = g_h[ping ^ 1];
    const int t  = threadIdx.x;
    const int n0 = blockIdx.x * 128;
    const int tx = t & 15;
    const int ty = t >> 4;
    const int col = tx * 8;

    float acc[8][8];
    {
        float4 b0 = *reinterpret_cast<const float4*>(B + col);
        float4 b1 = *reinterpret_cast<const float4*>(B + col + 4);
        float bb[8] = {b0.x,b0.y,b0.z,b0.w,b1.x,b1.y,b1.z,b1.w};
        #pragma unroll
        for (int i = 0; i < 8; i++)
            #pragma unroll
            for (int j = 0; j < 8; j++) acc[i][j] = bb[j];
    }

    for (int kt = 0; kt < 16; kt++) {
        const int k0 = kt * 16;
        __syncthreads();
        #pragma unroll
        for (int q = 0; q < 2; q++) {          // A tile 128x16
            int s = t * 2 + q;
            int r = s >> 2;
            int c = (s & 3) * 4;
            int n = n0 + r;
            if (n >= N_NODES) n = 0;
            const float* srcp = (k0 < 128)
                ? (h      + (size_t)n * HID + k0 + c)
                : (g_aggr + (size_t)n * HID + (k0 - 128) + c);
            float4 v = *reinterpret_cast<const float4*>(srcp);
            sA[r][c] = v.x; sA[r][c+1] = v.y; sA[r][c+2] = v.z; sA[r][c+3] = v.w;
        }
        #pragma unroll
        for (int q = 0; q < 2; q++) {          // W tile 16x128
            int s  = t * 2 + q;
            int kr = s >> 5;
            int c  = (s & 31) * 4;
            *reinterpret_cast<float4*>(&sB[kr][c]) =
                *reinterpret_cast<const float4*>(W + (size_t)(k0 + kr) * HID + c);
        }
        __syncthreads();
        #pragma unroll
        for (int k = 0; k < 16; k++) {
            float a[8];
            #pragma unroll
            for (int i = 0; i < 8; i++) a[i] = sA[ty*8 + i][k];
            float4 b0 = *reinterpret_cast<float4*>(&sB[k][col]);
            float4 b1 = *reinterpret_cast<float4*>(&sB[k][col + 4]);
            float bb[8] = {b0.x,b0.y,b0.z,b0.w,b1.x,b1.y,b1.z,b1.w};
            #pragma unroll
            for (int i = 0; i < 8; i++)
                #pragma unroll
                for (int j = 0; j < 8; j++)
                    acc[i][j] = fmaf(a[i], bb[j], acc[i][j]);
        }
    }

    float4 g0 = *reinterpret_cast<const float4*>(LG + col);
    float4 g1 = *reinterpret_cast<const float4*>(LG + col + 4);
    float4 lb0 = *reinterpret_cast<const float4*>(LB + col);
    float4 lb1 = *reinterpret_cast<const float4*>(LB + col + 4);
    float gg[8] = {g0.x,g0.y,g0.z,g0.w,g1.x,g1.y,g1.z,g1.w};
    float lbv[8] = {lb0.x,lb0.y,lb0.z,lb0.w,lb1.x,lb1.y,lb1.z,lb1.w};

    #pragma unroll
    for (int i = 0; i < 8; i++) {
        float s = 0.f, q = 0.f;
        #pragma unroll
        for (int j = 0; j < 8; j++) {
            acc[i][j] = fmaxf(acc[i][j], 0.f);
            s += acc[i][j]; q += acc[i][j] * acc[i][j];
        }
        #pragma unroll
        for (int m = 1; m < 16; m <<= 1) {
            s += __shfl_xor_sync(0xffffffffu, s, m);
            q += __shfl_xor_sync(0xffffffffu, q, m);
        }
        float mu  = s * (1.f / 128.f);
        float var = q * (1.f / 128.f) - mu * mu;
        float rs  = rsqrtf(var + 1e-5f);

        int n = n0 + ty * 8 + i;
        if (n < N_NODES) {
            const float* rp = h + (size_t)n * HID + col;
            float4 r0 = *reinterpret_cast<const float4*>(rp);
            float4 r1 = *reinterpret_cast<const float4*>(rp + 4);
            float rr[8] = {r0.x,r0.y,r0.z,r0.w,r1.x,r1.y,r1.z,r1.w};
            float o[8];
            #pragma unroll
            for (int j = 0; j < 8; j++) {
                float v = (acc[i][j] - mu) * rs * gg[j] + lbv[j];
                o[j] = fmaxf(v, 0.f) + rr[j];
            }
            float* op = hout + (size_t)n * HID + col;
            *reinterpret_cast<float4*>(op)     = make_float4(o[0],o[1],o[2],o[3]);
            *reinterpret_cast<float4*>(op + 4) = make_float4(o[4],o[5],o[6],o[7]);
        }
    }
}

// ================= pooling / readout =================
__global__ void pool_init_kernel() {
    int i = blockIdx.x * 256 + threadIdx.x;
    g_mean[i] = 0.f;
    g_maxe[i] = ENC_NEG_INF;
    if (i < NGRAPHS) g_cnt[i] = 0.f;
}

__global__ void pool_acc_kernel(int ping, const int* __restrict__ batch) {
    int idx = blockIdx.x * 256 + threadIdx.x;
    int n = idx >> 7, c = idx & 127;
    float v = g_h[ping][idx];
    int gph = batch[n];
    atomicAdd(&g_mean[gph * HID + c], v);
    atomicMax(&g_maxe[gph * HID + c], fenc(v));
    if (c == 0) atomicAdd(&g_cnt[gph], 1.f);
}

__global__ void readout_kernel(const float* __restrict__ W1,
                               const float* __restrict__ B1,
                               const float* __restrict__ W2,
                               const float* __restrict__ B2,
                               float* __restrict__ out)
{
    __shared__ float gv[256];
    __shared__ float red[128];
    const int g = blockIdx.x, t = threadIdx.x;
    float cnt = fmaxf(g_cnt[g], 1.f);
    gv[t]       = g_mean[g * HID + t] / cnt;
    gv[128 + t] = fdec(g_maxe[g * HID + t]);
    __syncthreads();
    float a = B1[t];
    #pragma unroll 8
    for (int k = 0; k < 256; k++)
        a = fmaf(gv[k], W1[(size_t)k * HID + t], a);
    a = fmaxf(a, 0.f) * W2[t];
    red[t] = a;
    __syncthreads();
    for (int s2 = 64; s2 > 0; s2 >>= 1) {
        if (t < s2) red[t] += red[t + s2];
        __syncthreads();
    }
    if (t == 0) out[g] = red[0] + B2[0];
}

// ================= launch =================
extern "C" void kernel_launch(void* const* d_in, const int* in_sizes, int n_in,
                              void* d_out, int out_size)
{
    const float* x     = (const float*)d_in[0];
    const int*   ei    = (const int*)  d_in[1];
    const float* eattr = (const float*)d_in[2];
    const int*   batch = (const int*)  d_in[3];
    const float* npw   = (const float*)d_in[4];
    const float* npb   = (const float*)d_in[5];
    const float* mw1   = (const float*)d_in[6];
    const float* mb1   = (const float*)d_in[7];
    const float* mw2   = (const float*)d_in[8];
    const float* mb2   = (const float*)d_in[9];
    const float* uw    = (const float*)d_in[10];
    const float* ub    = (const float*)d_in[11];
    const float* lg    = (const float*)d_in[12];
    const float* lb    = (const float*)d_in[13];
    const float* fw1   = (const float*)d_in[14];
    const float* fb1   = (const float*)d_in[15];
    const float* fw2   = (const float*)d_in[16];
    const float* fb2   = (const float*)d_in[17];
    float* out = (float*)d_out;

    const int* srcIdx = ei;
    const int* dstIdx = ei + N_EDGES;

    cudaFuncSetAttribute(msg_tc_kernel,
                         cudaFuncAttributeMaxDynamicSharedMemorySize,
                         SMEM_MSG_BYTES);

    node_proj_kernel<<<N_NODES / 16, 256>>>(x, npw, npb);

    int ping = 0;
    for (int l = 0; l < NLAYERS; l++) {
        zero_aggr_kernel<<<(N_NODES * HID) / 256, 256>>>();
        msg_tc_kernel<<<MSG_GRID, 256, SMEM_MSG_BYTES>>>(
            ping, eattr, srcIdx, dstIdx,
            mw1 + (size_t)l * (HID + EDGE_DIM) * HID, mb1 + (size_t)l * HID,
            mw2 + (size_t)l * HID * HID,              mb2 + (size_t)l * HID);
        update_kernel<<<(N_NODES + 127) / 128, 256>>>(
            ping,
            uw + (size_t)l * 2 * HID * HID, ub + (size_t)l * HID,
            lg + (size_t)l * HID,           lb + (size_t)l * HID);
        ping ^= 1;
    }

    pool_init_kernel<<<(NGRAPHS * HID) / 256, 256>>>();
    pool_acc_kernel<<<(N_NODES * HID) / 256, 256>>>(ping, batch);
    readout_kernel<<<NGRAPHS, 128>>>(fw1, fb1, fw2, fb2, out);
}

// round 4
// speedup vs baseline: 4.3418x; 2.0879x over previous
#include <cuda_runtime.h>
#include <cuda_bf16.h>
#include <cstdint>
#include <math.h>

#define N_NODES   20000
#define N_EDGES   640000
#define IN_CH     64
#define EDGE_DIM  16
#define HID       128
#define NLAYERS   3
#define NGRAPHS   128
#define ETILE     128
#define N_ETILES  (N_EDGES / ETILE)   // 5000

// ================= scratch (device globals) =================
__device__ float     g_h[2][N_NODES * HID];
__device__ float     g_P[N_NODES * HID];      // per-layer node pre-message
__device__ float     g_R[N_NODES * HID];      // scatter-accumulated relu(hidden)
__device__ float     g_wcomp[HID * HID];      // W2 @ Wu_bot (per layer)
__device__ float     g_bvec[HID];             // b2 @ Wu_bot (per layer)
__device__ float     g_deg[N_NODES];          // in-degree (dst counts)
__device__ float     g_mean[NGRAPHS * HID];
__device__ unsigned  g_maxe[NGRAPHS * HID];
__device__ float     g_cnt[NGRAPHS];

__device__ __forceinline__ unsigned fenc(float f) {
    unsigned u = __float_as_uint(f);
    return (u & 0x80000000u) ? ~u : (u | 0x80000000u);
}
__device__ __forceinline__ float fdec(unsigned u) {
    return (u & 0x80000000u) ? __uint_as_float(u & 0x7FFFFFFFu)
                             : __uint_as_float(~u);
}
#define ENC_NEG_INF 0x007FFFFFu

// ================= node projection: h0 = x @ W + b =================
__global__ void node_proj_kernel(const float* __restrict__ x,
                                 const float* __restrict__ W,
                                 const float* __restrict__ B) {
    __shared__ float sX[16][IN_CH];
    const int t  = threadIdx.x;
    const int n0 = blockIdx.x * 16;
    for (int i = t; i < 16 * IN_CH; i += 256) {
        int r = i >> 6, c = i & 63;
        sX[r][c] = x[(size_t)(n0 + r) * IN_CH + c];
    }
    __syncthreads();
    const int row = t >> 4;
    const int col = (t & 15) * 8;
    float acc[8];
    {
        float4 b0 = *reinterpret_cast<const float4*>(B + col);
        float4 b1 = *reinterpret_cast<const float4*>(B + col + 4);
        acc[0]=b0.x; acc[1]=b0.y; acc[2]=b0.z; acc[3]=b0.w;
        acc[4]=b1.x; acc[5]=b1.y; acc[6]=b1.z; acc[7]=b1.w;
    }
    #pragma unroll 8
    for (int k = 0; k < IN_CH; k++) {
        float a = sX[row][k];
        float4 w0 = *reinterpret_cast<const float4*>(W + (size_t)k * HID + col);
        float4 w1 = *reinterpret_cast<const float4*>(W + (size_t)k * HID + col + 4);
        acc[0] = fmaf(a, w0.x, acc[0]); acc[1] = fmaf(a, w0.y, acc[1]);
        acc[2] = fmaf(a, w0.z, acc[2]); acc[3] = fmaf(a, w0.w, acc[3]);
        acc[4] = fmaf(a, w1.x, acc[4]); acc[5] = fmaf(a, w1.y, acc[5]);
        acc[6] = fmaf(a, w1.z, acc[6]); acc[7] = fmaf(a, w1.w, acc[7]);
    }
    float* out = g_h[0] + (size_t)(n0 + row) * HID + col;
    *reinterpret_cast<float4*>(out)     = make_float4(acc[0], acc[1], acc[2], acc[3]);
    *reinterpret_cast<float4*>(out + 4) = make_float4(acc[4], acc[5], acc[6], acc[7]);
}

// ================= degree (once; graph fixed across layers) =================
__global__ void deg_zero_kernel() {
    int i = blockIdx.x * 256 + threadIdx.x;
    if (i < N_NODES) g_deg[i] = 0.f;
}
__global__ void deg_count_kernel(const int* __restrict__ dstIdx) {
    int i = blockIdx.x * 256 + threadIdx.x;
    atomicAdd(&g_deg[dstIdx[i]], 1.f);
}

__global__ void zero_R_kernel() {
    int i = blockIdx.x * 256 + threadIdx.x;   // 2500 blocks, float4
    reinterpret_cast<float4*>(g_R)[i] = make_float4(0.f, 0.f, 0.f, 0.f);
}

// ================= pre: P = h @ W1[:128] + b1  (node-level, fp32) =========
__global__ void __launch_bounds__(256, 1) pre_kernel(
    int ping, const float* __restrict__ W, const float* __restrict__ B)
{
    __shared__ float sA[128][17];
    __shared__ float sB[16][128];
    const float* __restrict__ h = g_h[ping];
    const int t  = threadIdx.x;
    const int n0 = blockIdx.x * 128;
    const int tx = t & 15;
    const int ty = t >> 4;
    const int col = tx * 8;

    float acc[8][8];
    {
        float4 b0 = *reinterpret_cast<const float4*>(B + col);
        float4 b1 = *reinterpret_cast<const float4*>(B + col + 4);
        float bb[8] = {b0.x,b0.y,b0.z,b0.w,b1.x,b1.y,b1.z,b1.w};
        #pragma unroll
        for (int i = 0; i < 8; i++)
            #pragma unroll
            for (int j = 0; j < 8; j++) acc[i][j] = bb[j];
    }

    for (int kt = 0; kt < 8; kt++) {
        const int k0 = kt * 16;
        __syncthreads();
        #pragma unroll
        for (int q = 0; q < 2; q++) {          // A tile 128x16
            int s = t * 2 + q;
            int r = s >> 2;
            int c = (s & 3) * 4;
            int n = n0 + r;
            if (n >= N_NODES) n = 0;
            float4 v = *reinterpret_cast<const float4*>(h + (size_t)n * HID + k0 + c);
            sA[r][c] = v.x; sA[r][c+1] = v.y; sA[r][c+2] = v.z; sA[r][c+3] = v.w;
        }
        #pragma unroll
        for (int q = 0; q < 2; q++) {          // W tile 16x128
            int s  = t * 2 + q;
            int kr = s >> 5;
            int c  = (s & 31) * 4;
            *reinterpret_cast<float4*>(&sB[kr][c]) =
                *reinterpret_cast<const float4*>(W + (size_t)(k0 + kr) * HID + c);
        }
        __syncthreads();
        #pragma unroll
        for (int k = 0; k < 16; k++) {
            float a[8];
            #pragma unroll
            for (int i = 0; i < 8; i++) a[i] = sA[ty*8 + i][k];
            float4 b0 = *reinterpret_cast<float4*>(&sB[k][col]);
            float4 b1 = *reinterpret_cast<float4*>(&sB[k][col + 4]);
            float bb[8] = {b0.x,b0.y,b0.z,b0.w,b1.x,b1.y,b1.z,b1.w};
            #pragma unroll
            for (int i = 0; i < 8; i++)
                #pragma unroll
                for (int j = 0; j < 8; j++)
                    acc[i][j] = fmaf(a[i], bb[j], acc[i][j]);
        }
    }

    #pragma unroll
    for (int i = 0; i < 8; i++) {
        int n = n0 + ty * 8 + i;
        if (n < N_NODES) {
            float* op = g_P + (size_t)n * HID + col;
            *reinterpret_cast<float4*>(op)     = make_float4(acc[i][0],acc[i][1],acc[i][2],acc[i][3]);
            *reinterpret_cast<float4*>(op + 4) = make_float4(acc[i][4],acc[i][5],acc[i][6],acc[i][7]);
        }
    }
}

// ================= compose: Wcomp = W2 @ Wu_bot ; bvec = b2 @ Wu_bot ======
__global__ void compose_kernel(const float* __restrict__ W2,
                               const float* __restrict__ WuBot,
                               const float* __restrict__ b2)
{
    int idx = blockIdx.x * 256 + threadIdx.x;   // 64 blocks x 256 = 16384
    int j   = idx >> 7;
    int out = idx & 127;
    float acc = 0.f;
    #pragma unroll 8
    for (int c = 0; c < HID; c++)
        acc = fmaf(W2[(size_t)j * HID + c], WuBot[(size_t)c * HID + out], acc);
    g_wcomp[(size_t)j * HID + out] = acc;
    if (idx < HID) {
        float bv = 0.f;
        #pragma unroll 8
        for (int c = 0; c < HID; c++)
            bv = fmaf(b2[c], WuBot[(size_t)c * HID + out], bv);
        g_bvec[out] = bv;
    }
}

// ================= edge kernel: R[dst] += relu(P[src] + ea @ W1e) =========
// one warp per edge per pass; W1e register-resident; red.v4 scatter
__global__ void edge_kernel(
    const float* __restrict__ eattr,
    const int*   __restrict__ srcIdx,
    const int*   __restrict__ dstIdx,
    const float* __restrict__ W1e)     // rows 128..143 of msg_w1[l]
{
    __shared__ int sSrc[ETILE], sDst[ETILE];
    const int t    = threadIdx.x;
    const int lane = t & 31;
    const int warp = t >> 5;
    const int e0   = blockIdx.x * ETILE;

    if (t < ETILE) { sSrc[t] = srcIdx[e0 + t]; sDst[t] = dstIdx[e0 + t]; }

    float4 w[16];
    #pragma unroll
    for (int k = 0; k < 16; k++)
        w[k] = *reinterpret_cast<const float4*>(W1e + (size_t)k * HID + lane * 4);
    __syncthreads();

    #pragma unroll 2
    for (int pass = 0; pass < 16; pass++) {
        const int e   = pass * 8 + warp;
        const int src = sSrc[e];
        float eav = (lane < EDGE_DIM)
                  ? eattr[(size_t)(e0 + e) * EDGE_DIM + lane] : 0.f;
        float4 p = *reinterpret_cast<const float4*>(
            g_P + (size_t)src * HID + lane * 4);
        float a0 = p.x, a1 = p.y, a2 = p.z, a3 = p.w;
        #pragma unroll
        for (int k = 0; k < 16; k++) {
            float a = __shfl_sync(0xffffffffu, eav, k);
            a0 = fmaf(a, w[k].x, a0); a1 = fmaf(a, w[k].y, a1);
            a2 = fmaf(a, w[k].z, a2); a3 = fmaf(a, w[k].w, a3);
        }
        a0 = fmaxf(a0, 0.f); a1 = fmaxf(a1, 0.f);
        a2 = fmaxf(a2, 0.f); a3 = fmaxf(a3, 0.f);
        float* rp = g_R + (size_t)sDst[e] * HID + lane * 4;
        asm volatile("red.global.add.v4.f32 [%0], {%1,%2,%3,%4};"
                     :: "l"(rp), "f"(a0), "f"(a1), "f"(a2), "f"(a3)
                     : "memory");
    }
}

// ====== update: u = relu(h@Wu_top + R@Wcomp + deg*bvec + b); LN; +res =====
__global__ void __launch_bounds__(256, 1) update_kernel(
    int ping,
    const float* __restrict__ Wtop,    // upd_w[l] rows 0..127
    const float* __restrict__ B,
    const float* __restrict__ LG,
    const float* __restrict__ LB)
{
    __shared__ float sA[128][17];
    __shared__ float sB[16][128];
    __shared__ float sDeg[128];
    const float* __restrict__ h    = g_h[ping];
    float*       __restrict__ hout = g_h[ping ^ 1];
    const int t  = threadIdx.x;
    const int n0 = blockIdx.x * 128;
    const int tx = t & 15;
    const int ty = t >> 4;
    const int col = tx * 8;

    if (t < 128) {
        int n = n0 + t;
        sDeg[t] = (n < N_NODES) ? g_deg[n] : 0.f;
    }

    float acc[8][8];
    {
        float4 b0 = *reinterpret_cast<const float4*>(B + col);
        float4 b1 = *reinterpret_cast<const float4*>(B + col + 4);
        float bb[8] = {b0.x,b0.y,b0.z,b0.w,b1.x,b1.y,b1.z,b1.w};
        #pragma unroll
        for (int i = 0; i < 8; i++)
            #pragma unroll
            for (int j = 0; j < 8; j++) acc[i][j] = bb[j];
    }

    for (int kt = 0; kt < 16; kt++) {
        const int k0 = kt * 16;
        __syncthreads();
        #pragma unroll
        for (int q = 0; q < 2; q++) {          // A tile 128x16 (h | R)
            int s = t * 2 + q;
            int r = s >> 2;
            int c = (s & 3) * 4;
            int n = n0 + r;
            if (n >= N_NODES) n = 0;
            const float* srcp = (k0 < 128)
                ? (h   + (size_t)n * HID + k0 + c)
                : (g_R + (size_t)n * HID + (k0 - 128) + c);
            float4 v = *reinterpret_cast<const float4*>(srcp);
            sA[r][c] = v.x; sA[r][c+1] = v.y; sA[r][c+2] = v.z; sA[r][c+3] = v.w;
        }
        #pragma unroll
        for (int q = 0; q < 2; q++) {          // W tile 16x128 (Wtop | Wcomp)
            int s  = t * 2 + q;
            int kr = s >> 5;
            int c  = (s & 31) * 4;
            const float* wp = (k0 < 128)
                ? (Wtop    + (size_t)(k0 + kr) * HID + c)
                : (g_wcomp + (size_t)(k0 - 128 + kr) * HID + c);
            *reinterpret_cast<float4*>(&sB[kr][c]) =
                *reinterpret_cast<const float4*>(wp);
        }
        __syncthreads();
        #pragma unroll
        for (int k = 0; k < 16; k++) {
            float a[8];
            #pragma unroll
            for (int i = 0; i < 8; i++) a[i] = sA[ty*8 + i][k];
            float4 b0 = *reinterpret_cast<float4*>(&sB[k][col]);
            float4 b1 = *reinterpret_cast<float4*>(&sB[k][col + 4]);
            float bb[8] = {b0.x,b0.y,b0.z,b0.w,b1.x,b1.y,b1.z,b1.w};
            #pragma unroll
            for (int i = 0; i < 8; i++)
                #pragma unroll
                for (int j = 0; j < 8; j++)
                    acc[i][j] = fmaf(a[i], bb[j], acc[i][j]);
        }
    }

    float4 g0  = *reinterpret_cast<const float4*>(LG + col);
    float4 g1  = *reinterpret_cast<const float4*>(LG + col + 4);
    float4 lb0 = *reinterpret_cast<const float4*>(LB + col);
    float4 lb1 = *reinterpret_cast<const float4*>(LB + col + 4);
    float4 bv0 = *reinterpret_cast<const float4*>(g_bvec + col);
    float4 bv1 = *reinterpret_cast<const float4*>(g_bvec + col + 4);
    float gg[8]  = {g0.x,g0.y,g0.z,g0.w,g1.x,g1.y,g1.z,g1.w};
    float lbv[8] = {lb0.x,lb0.y,lb0.z,lb0.w,lb1.x,lb1.y,lb1.z,lb1.w};
    float bvv[8] = {bv0.x,bv0.y,bv0.z,bv0.w,bv1.x,bv1.y,bv1.z,bv1.w};

    #pragma unroll
    for (int i = 0; i < 8; i++) {
        float dg = sDeg[ty * 8 + i];
        float s = 0.f, q = 0.f;
        #pragma unroll
        for (int j = 0; j < 8; j++) {
            acc[i][j] = fmaxf(acc[i][j] + dg * bvv[j], 0.f);
            s += acc[i][j]; q += acc[i][j] * acc[i][j];
        }
        #pragma unroll
        for (int m = 1; m < 16; m <<= 1) {
            s += __shfl_xor_sync(0xffffffffu, s, m);
            q += __shfl_xor_sync(0xffffffffu, q, m);
        }
        float mu  = s * (1.f / 128.f);
        float var = q * (1.f / 128.f) - mu * mu;
        float rs  = rsqrtf(var + 1e-5f);

        int n = n0 + ty * 8 + i;
        if (n < N_NODES) {
            const float* rp = h + (size_t)n * HID + col;
            float4 r0 = *reinterpret_cast<const float4*>(rp);
            float4 r1 = *reinterpret_cast<const float4*>(rp + 4);
            float rr[8] = {r0.x,r0.y,r0.z,r0.w,r1.x,r1.y,r1.z,r1.w};
            float o[8];
            #pragma unroll
            for (int j = 0; j < 8; j++) {
                float v = (acc[i][j] - mu) * rs * gg[j] + lbv[j];
                o[j] = fmaxf(v, 0.f) + rr[j];
            }
            float* op = hout + (size_t)n * HID + col;
            *reinterpret_cast<float4*>(op)     = make_float4(o[0],o[1],o[2],o[3]);
            *reinterpret_cast<float4*>(op + 4) = make_float4(o[4],o[5],o[6],o[7]);
        }
    }
}

// ================= pooling / readout =================
__global__ void pool_init_kernel() {
    int i = blockIdx.x * 256 + threadIdx.x;
    g_mean[i] = 0.f;
    g_maxe[i] = ENC_NEG_INF;
    if (i < NGRAPHS) g_cnt[i] = 0.f;
}

__global__ void pool_acc_kernel(int ping, const int* __restrict__ batch) {
    int idx = blockIdx.x * 256 + threadIdx.x;
    int n = idx >> 7, c = idx & 127;
    float v = g_h[ping][idx];
    int gph = batch[n];
    atomicAdd(&g_mean[gph * HID + c], v);
    atomicMax(&g_maxe[gph * HID + c], fenc(v));
    if (c == 0) atomicAdd(&g_cnt[gph], 1.f);
}

__global__ void readout_kernel(const float* __restrict__ W1,
                               const float* __restrict__ B1,
                               const float* __restrict__ W2,
                               const float* __restrict__ B2,
                               float* __restrict__ out)
{
    __shared__ float gv[256];
    __shared__ float red[128];
    const int g = blockIdx.x, t = threadIdx.x;
    float cnt = fmaxf(g_cnt[g], 1.f);
    gv[t]       = g_mean[g * HID + t] / cnt;
    gv[128 + t] = fdec(g_maxe[g * HID + t]);
    __syncthreads();
    float a = B1[t];
    #pragma unroll 8
    for (int k = 0; k < 256; k++)
        a = fmaf(gv[k], W1[(size_t)k * HID + t], a);
    a = fmaxf(a, 0.f) * W2[t];
    red[t] = a;
    __syncthreads();
    for (int s2 = 64; s2 > 0; s2 >>= 1) {
        if (t < s2) red[t] += red[t + s2];
        __syncthreads();
    }
    if (t == 0) out[g] = red[0] + B2[0];
}

// ================= launch =================
extern "C" void kernel_launch(void* const* d_in, const int* in_sizes, int n_in,
                              void* d_out, int out_size)
{
    const float* x     = (const float*)d_in[0];
    const int*   ei    = (const int*)  d_in[1];
    const float* eattr = (const float*)d_in[2];
    const int*   batch = (const int*)  d_in[3];
    const float* npw   = (const float*)d_in[4];
    const float* npb   = (const float*)d_in[5];
    const float* mw1   = (const float*)d_in[6];
    const float* mb1   = (const float*)d_in[7];
    const float* mw2   = (const float*)d_in[8];
    const float* mb2   = (const float*)d_in[9];
    const float* uw    = (const float*)d_in[10];
    const float* ub    = (const float*)d_in[11];
    const float* lg    = (const float*)d_in[12];
    const float* lb    = (const float*)d_in[13];
    const float* fw1   = (const float*)d_in[14];
    const float* fb1   = (const float*)d_in[15];
    const float* fw2   = (const float*)d_in[16];
    const float* fb2   = (const float*)d_in[17];
    float* out = (float*)d_out;

    const int* srcIdx = ei;
    const int* dstIdx = ei + N_EDGES;

    node_proj_kernel<<<N_NODES / 16, 256>>>(x, npw, npb);
    deg_zero_kernel<<<(N_NODES + 255) / 256, 256>>>();
    deg_count_kernel<<<N_EDGES / 256, 256>>>(dstIdx);

    int ping = 0;
    for (int l = 0; l < NLAYERS; l++) {
        const float* W1l  = mw1 + (size_t)l * (HID + EDGE_DIM) * HID;
        const float* W1el = W1l + (size_t)HID * HID;         // eattr rows
        const float* W2l  = mw2 + (size_t)l * HID * HID;
        const float* Wul  = uw  + (size_t)l * 2 * HID * HID; // rows 0..255
        const float* WuBot= Wul + (size_t)HID * HID;

        pre_kernel<<<(N_NODES + 127) / 128, 256>>>(ping, W1l, mb1 + (size_t)l * HID);
        zero_R_kernel<<<(N_NODES * HID / 4) / 256, 256>>>();
        compose_kernel<<<64, 256>>>(W2l, WuBot, mb2 + (size_t)l * HID);
        edge_kernel<<<N_ETILES, 256>>>(eattr, srcIdx, dstIdx, W1el);
        update_kernel<<<(N_NODES + 127) / 128, 256>>>(
            ping, Wul, ub + (size_t)l * HID,
            lg + (size_t)l * HID, lb + (size_t)l * HID);
        ping ^= 1;
    }

    pool_init_kernel<<<(NGRAPHS * HID) / 256, 256>>>();
    pool_acc_kernel<<<(N_NODES * HID) / 256, 256>>>(ping, batch);
    readout_kernel<<<NGRAPHS, 128>>>(fw1, fb1, fw2, fb2, out);
}

// round 6
// speedup vs baseline: 5.2347x; 1.2056x over previous
#include <cuda_runtime.h>
#include <cuda_bf16.h>
#include <cstdint>
#include <math.h>

#define N_NODES   20000
#define N_EDGES   640000
#define IN_CH     64
#define EDGE_DIM  16
#define HID       128
#define NLAYERS   3
#define NGRAPHS   128
#define ETILE     128
#define N_ETILES  (N_EDGES / ETILE)   // 5000

// ================= scratch (device globals) =================
__device__ float     g_h[2][N_NODES * HID];
__device__ float     g_P[N_NODES * HID];      // node pre-message (per layer)
__device__ float     g_R[N_NODES * HID];      // scatter-accumulated relu(hidden)
__device__ float     g_wcomp[HID * HID];      // W2 @ Wu_bot (per layer)
__device__ float     g_bvec[HID];             // b2 @ Wu_bot (per layer)
__device__ float     g_deg[N_NODES];
__device__ float     g_mean[NGRAPHS * HID];
__device__ unsigned  g_maxe[NGRAPHS * HID];
__device__ float     g_cnt[NGRAPHS];

__device__ __forceinline__ unsigned fenc(float f) {
    unsigned u = __float_as_uint(f);
    return (u & 0x80000000u) ? ~u : (u | 0x80000000u);
}
__device__ __forceinline__ float fdec(unsigned u) {
    return (u & 0x80000000u) ? __uint_as_float(u & 0x7FFFFFFFu)
                             : __uint_as_float(~u);
}
#define ENC_NEG_INF 0x007FFFFFu

// ================= node projection: h0 = x @ W + b =================
__global__ void node_proj_kernel(const float* __restrict__ x,
                                 const float* __restrict__ W,
                                 const float* __restrict__ B) {
    __shared__ float sX[16][IN_CH];
    const int t  = threadIdx.x;
    const int n0 = blockIdx.x * 16;
    for (int i = t; i < 16 * IN_CH; i += 256) {
        int r = i >> 6, c = i & 63;
        sX[r][c] = x[(size_t)(n0 + r) * IN_CH + c];
    }
    __syncthreads();
    const int row = t >> 4;
    const int col = (t & 15) * 8;
    float acc[8];
    {
        float4 b0 = *reinterpret_cast<const float4*>(B + col);
        float4 b1 = *reinterpret_cast<const float4*>(B + col + 4);
        acc[0]=b0.x; acc[1]=b0.y; acc[2]=b0.z; acc[3]=b0.w;
        acc[4]=b1.x; acc[5]=b1.y; acc[6]=b1.z; acc[7]=b1.w;
    }
    #pragma unroll 8
    for (int k = 0; k < IN_CH; k++) {
        float a = sX[row][k];
        float4 w0 = *reinterpret_cast<const float4*>(W + (size_t)k * HID + col);
        float4 w1 = *reinterpret_cast<const float4*>(W + (size_t)k * HID + col + 4);
        acc[0] = fmaf(a, w0.x, acc[0]); acc[1] = fmaf(a, w0.y, acc[1]);
        acc[2] = fmaf(a, w0.z, acc[2]); acc[3] = fmaf(a, w0.w, acc[3]);
        acc[4] = fmaf(a, w1.x, acc[4]); acc[5] = fmaf(a, w1.y, acc[5]);
        acc[6] = fmaf(a, w1.z, acc[6]); acc[7] = fmaf(a, w1.w, acc[7]);
    }
    float* out = g_h[0] + (size_t)(n0 + row) * HID + col;
    *reinterpret_cast<float4*>(out)     = make_float4(acc[0], acc[1], acc[2], acc[3]);
    *reinterpret_cast<float4*>(out + 4) = make_float4(acc[4], acc[5], acc[6], acc[7]);
}

// ================= degree =================
__global__ void deg_zero_kernel() {
    int i = blockIdx.x * 256 + threadIdx.x;
    if (i < N_NODES) g_deg[i] = 0.f;
}
__global__ void deg_count_kernel(const int* __restrict__ dstIdx) {
    int i = blockIdx.x * 256 + threadIdx.x;
    atomicAdd(&g_deg[dstIdx[i]], 1.f);
}

__global__ void zero_R_kernel() {
    int i = blockIdx.x * 256 + threadIdx.x;
    reinterpret_cast<float4*>(g_R)[i] = make_float4(0.f, 0.f, 0.f, 0.f);
}

// ================= pre (layer 0 only): P = h @ W1[:128] + b1 =========
__global__ void __launch_bounds__(256, 1) pre_kernel(
    int ping, const float* __restrict__ W, const float* __restrict__ B)
{
    __shared__ float sA[128][17];
    __shared__ float sB[16][128];
    const float* __restrict__ h = g_h[ping];
    const int t  = threadIdx.x;
    const int n0 = blockIdx.x * 128;
    const int tx = t & 15;
    const int ty = t >> 4;
    const int col = tx * 8;

    float acc[8][8];
    {
        float4 b0 = *reinterpret_cast<const float4*>(B + col);
        float4 b1 = *reinterpret_cast<const float4*>(B + col + 4);
        float bb[8] = {b0.x,b0.y,b0.z,b0.w,b1.x,b1.y,b1.z,b1.w};
        #pragma unroll
        for (int i = 0; i < 8; i++)
            #pragma unroll
            for (int j = 0; j < 8; j++) acc[i][j] = bb[j];
    }

    for (int kt = 0; kt < 8; kt++) {
        const int k0 = kt * 16;
        __syncthreads();
        #pragma unroll
        for (int q = 0; q < 2; q++) {
            int s = t * 2 + q;
            int r = s >> 2;
            int c = (s & 3) * 4;
            int n = n0 + r;
            if (n >= N_NODES) n = 0;
            float4 v = *reinterpret_cast<const float4*>(h + (size_t)n * HID + k0 + c);
            sA[r][c] = v.x; sA[r][c+1] = v.y; sA[r][c+2] = v.z; sA[r][c+3] = v.w;
        }
        #pragma unroll
        for (int q = 0; q < 2; q++) {
            int s  = t * 2 + q;
            int kr = s >> 5;
            int c  = (s & 31) * 4;
            *reinterpret_cast<float4*>(&sB[kr][c]) =
                *reinterpret_cast<const float4*>(W + (size_t)(k0 + kr) * HID + c);
        }
        __syncthreads();
        #pragma unroll
        for (int k = 0; k < 16; k++) {
            float a[8];
            #pragma unroll
            for (int i = 0; i < 8; i++) a[i] = sA[ty*8 + i][k];
            float4 b0 = *reinterpret_cast<float4*>(&sB[k][col]);
            float4 b1 = *reinterpret_cast<float4*>(&sB[k][col + 4]);
            float bb[8] = {b0.x,b0.y,b0.z,b0.w,b1.x,b1.y,b1.z,b1.w};
            #pragma unroll
            for (int i = 0; i < 8; i++)
                #pragma unroll
                for (int j = 0; j < 8; j++)
                    acc[i][j] = fmaf(a[i], bb[j], acc[i][j]);
        }
    }

    #pragma unroll
    for (int i = 0; i < 8; i++) {
        int n = n0 + ty * 8 + i;
        if (n < N_NODES) {
            float* op = g_P + (size_t)n * HID + col;
            *reinterpret_cast<float4*>(op)     = make_float4(acc[i][0],acc[i][1],acc[i][2],acc[i][3]);
            *reinterpret_cast<float4*>(op + 4) = make_float4(acc[i][4],acc[i][5],acc[i][6],acc[i][7]);
        }
    }
}

// ================= compose: Wcomp = W2 @ Wu_bot ; bvec = b2 @ Wu_bot ======
__global__ void compose_kernel(const float* __restrict__ W2,
                               const float* __restrict__ WuBot,
                               const float* __restrict__ b2)
{
    int idx = blockIdx.x * 256 + threadIdx.x;
    int j   = idx >> 7;
    int out = idx & 127;
    float acc = 0.f;
    #pragma unroll 8
    for (int c = 0; c < HID; c++)
        acc = fmaf(W2[(size_t)j * HID + c], WuBot[(size_t)c * HID + out], acc);
    g_wcomp[(size_t)j * HID + out] = acc;
    if (idx < HID) {
        float bv = 0.f;
        #pragma unroll 8
        for (int c = 0; c < HID; c++)
            bv = fmaf(b2[c], WuBot[(size_t)c * HID + out], bv);
        g_bvec[out] = bv;
    }
}

// ================= edge kernel: R[dst] += relu(P[src] + ea @ W1e) =========
__global__ void __launch_bounds__(256) edge_kernel(
    const float* __restrict__ eattr,
    const int*   __restrict__ srcIdx,
    const int*   __restrict__ dstIdx,
    const float* __restrict__ W1e)
{
    __shared__ float sEA[ETILE][EDGE_DIM];
    __shared__ int sSrc[ETILE], sDst[ETILE];
    const int t    = threadIdx.x;
    const int lane = t & 31;
    const int warp = t >> 5;
    const int e0   = blockIdx.x * ETILE;

    if (t < ETILE) { sSrc[t] = srcIdx[e0 + t]; sDst[t] = dstIdx[e0 + t]; }

    {
        const float4* ea4 = reinterpret_cast<const float4*>(
            eattr + (size_t)e0 * EDGE_DIM);
        float4* s4 = reinterpret_cast<float4*>(&sEA[0][0]);
        s4[t]       = ea4[t];
        s4[t + 256] = ea4[t + 256];
    }

    float4 w[16];
    #pragma unroll
    for (int k = 0; k < 16; k++)
        w[k] = *reinterpret_cast<const float4*>(W1e + (size_t)k * HID + lane * 4);
    __syncthreads();

    #pragma unroll
    for (int pass = 0; pass < 16; pass += 2) {
        const int ea = pass * 8 + warp;
        const int eb = ea + 8;
        const int sa = sSrc[ea];
        const int sb = sSrc[eb];
        float4 pa = *reinterpret_cast<const float4*>(
            g_P + (size_t)sa * HID + lane * 4);
        float4 pb = *reinterpret_cast<const float4*>(
            g_P + (size_t)sb * HID + lane * 4);
        float a0 = pa.x, a1 = pa.y, a2 = pa.z, a3 = pa.w;
        float b0 = pb.x, b1 = pb.y, b2 = pb.z, b3 = pb.w;
        #pragma unroll
        for (int k = 0; k < 16; k++) {
            float ak = sEA[ea][k];
            float bk = sEA[eb][k];
            a0 = fmaf(ak, w[k].x, a0); a1 = fmaf(ak, w[k].y, a1);
            a2 = fmaf(ak, w[k].z, a2); a3 = fmaf(ak, w[k].w, a3);
            b0 = fmaf(bk, w[k].x, b0); b1 = fmaf(bk, w[k].y, b1);
            b2 = fmaf(bk, w[k].z, b2); b3 = fmaf(bk, w[k].w, b3);
        }
        a0 = fmaxf(a0, 0.f); a1 = fmaxf(a1, 0.f);
        a2 = fmaxf(a2, 0.f); a3 = fmaxf(a3, 0.f);
        b0 = fmaxf(b0, 0.f); b1 = fmaxf(b1, 0.f);
        b2 = fmaxf(b2, 0.f); b3 = fmaxf(b3, 0.f);
        float* ra = g_R + (size_t)sDst[ea] * HID + lane * 4;
        float* rb = g_R + (size_t)sDst[eb] * HID + lane * 4;
        asm volatile("red.global.add.v4.f32 [%0], {%1,%2,%3,%4};"
                     :: "l"(ra), "f"(a0), "f"(a1), "f"(a2), "f"(a3) : "memory");
        asm volatile("red.global.add.v4.f32 [%0], {%1,%2,%3,%4};"
                     :: "l"(rb), "f"(b0), "f"(b1), "f"(b2), "f"(b3) : "memory");
    }
}

// ====== fused update: h' = relu(LN(relu([h,R]@Wu + deg*bvec + b)))+h ======
// then (if hasNext) P = h' @ W1next + b1next, with h' staged in a FULL
// 128x132 dynamic-SMEM tile (round-5 bug: tile was [128][17]).
#define SH_STRIDE 132
#define UPD_OFF_SA   0                              // 128*17*4   = 8704
#define UPD_OFF_SB   8704                           // 16*128*4   = 8192
#define UPD_OFF_SH   16896                          // 128*132*4  = 67584
#define UPD_OFF_DEG  84480                          // 128*4      = 512
#define UPD_SMEM_BYTES 84992

__global__ void __launch_bounds__(256, 1) update_kernel(
    int ping,
    const float* __restrict__ Wtop,
    const float* __restrict__ B,
    const float* __restrict__ LG,
    const float* __restrict__ LB,
    const float* __restrict__ W1n,
    const float* __restrict__ B1n,
    int hasNext)
{
    extern __shared__ char usm[];
    float (*sA)[17]  = (float(*)[17])(usm + UPD_OFF_SA);
    float (*sB)[128] = (float(*)[128])(usm + UPD_OFF_SB);
    float* sH        = (float*)(usm + UPD_OFF_SH);
    float* sDeg      = (float*)(usm + UPD_OFF_DEG);

    const float* __restrict__ h    = g_h[ping];
    float*       __restrict__ hout = g_h[ping ^ 1];
    const int t  = threadIdx.x;
    const int n0 = blockIdx.x * 128;
    const int tx = t & 15;
    const int ty = t >> 4;
    const int col = tx * 8;

    if (t < 128) {
        int n = n0 + t;
        sDeg[t] = (n < N_NODES) ? g_deg[n] : 0.f;
    }

    float acc[8][8];
    {
        float4 b0 = *reinterpret_cast<const float4*>(B + col);
        float4 b1 = *reinterpret_cast<const float4*>(B + col + 4);
        float bb[8] = {b0.x,b0.y,b0.z,b0.w,b1.x,b1.y,b1.z,b1.w};
        #pragma unroll
        for (int i = 0; i < 8; i++)
            #pragma unroll
            for (int j = 0; j < 8; j++) acc[i][j] = bb[j];
    }

    for (int kt = 0; kt < 16; kt++) {
        const int k0 = kt * 16;
        __syncthreads();
        #pragma unroll
        for (int q = 0; q < 2; q++) {
            int s = t * 2 + q;
            int r = s >> 2;
            int c = (s & 3) * 4;
            int n = n0 + r;
            if (n >= N_NODES) n = 0;
            const float* srcp = (k0 < 128)
                ? (h   + (size_t)n * HID + k0 + c)
                : (g_R + (size_t)n * HID + (k0 - 128) + c);
            float4 v = *reinterpret_cast<const float4*>(srcp);
            sA[r][c] = v.x; sA[r][c+1] = v.y; sA[r][c+2] = v.z; sA[r][c+3] = v.w;
        }
        #pragma unroll
        for (int q = 0; q < 2; q++) {
            int s  = t * 2 + q;
            int kr = s >> 5;
            int c  = (s & 31) * 4;
            const float* wp = (k0 < 128)
                ? (Wtop    + (size_t)(k0 + kr) * HID + c)
                : (g_wcomp + (size_t)(k0 - 128 + kr) * HID + c);
            *reinterpret_cast<float4*>(&sB[kr][c]) =
                *reinterpret_cast<const float4*>(wp);
        }
        __syncthreads();
        #pragma unroll
        for (int k = 0; k < 16; k++) {
            float a[8];
            #pragma unroll
            for (int i = 0; i < 8; i++) a[i] = sA[ty*8 + i][k];
            float4 b0 = *reinterpret_cast<float4*>(&sB[k][col]);
            float4 b1 = *reinterpret_cast<float4*>(&sB[k][col + 4]);
            float bb[8] = {b0.x,b0.y,b0.z,b0.w,b1.x,b1.y,b1.z,b1.w};
            #pragma unroll
            for (int i = 0; i < 8; i++)
                #pragma unroll
                for (int j = 0; j < 8; j++)
                    acc[i][j] = fmaf(a[i], bb[j], acc[i][j]);
        }
    }

    float4 g0  = *reinterpret_cast<const float4*>(LG + col);
    float4 g1  = *reinterpret_cast<const float4*>(LG + col + 4);
    float4 lb0 = *reinterpret_cast<const float4*>(LB + col);
    float4 lb1 = *reinterpret_cast<const float4*>(LB + col + 4);
    float4 bv0 = *reinterpret_cast<const float4*>(g_bvec + col);
    float4 bv1 = *reinterpret_cast<const float4*>(g_bvec + col + 4);
    float gg[8]  = {g0.x,g0.y,g0.z,g0.w,g1.x,g1.y,g1.z,g1.w};
    float lbv[8] = {lb0.x,lb0.y,lb0.z,lb0.w,lb1.x,lb1.y,lb1.z,lb1.w};
    float bvv[8] = {bv0.x,bv0.y,bv0.z,bv0.w,bv1.x,bv1.y,bv1.z,bv1.w};

    #pragma unroll
    for (int i = 0; i < 8; i++) {
        float dg = sDeg[ty * 8 + i];
        float s = 0.f, q = 0.f;
        #pragma unroll
        for (int j = 0; j < 8; j++) {
            acc[i][j] = fmaxf(acc[i][j] + dg * bvv[j], 0.f);
            s += acc[i][j]; q += acc[i][j] * acc[i][j];
        }
        #pragma unroll
        for (int m = 1; m < 16; m <<= 1) {
            s += __shfl_xor_sync(0xffffffffu, s, m);
            q += __shfl_xor_sync(0xffffffffu, q, m);
        }
        float mu  = s * (1.f / 128.f);
        float var = q * (1.f / 128.f) - mu * mu;
        float rs  = rsqrtf(var + 1e-5f);

        int n = n0 + ty * 8 + i;
        if (n < N_NODES) {
            const float* rp = h + (size_t)n * HID + col;
            float4 r0 = *reinterpret_cast<const float4*>(rp);
            float4 r1 = *reinterpret_cast<const float4*>(rp + 4);
            float rr[8] = {r0.x,r0.y,r0.z,r0.w,r1.x,r1.y,r1.z,r1.w};
            float o[8];
            #pragma unroll
            for (int j = 0; j < 8; j++) {
                float v = (acc[i][j] - mu) * rs * gg[j] + lbv[j];
                o[j] = fmaxf(v, 0.f) + rr[j];
            }
            float* sp = sH + (ty*8 + i) * SH_STRIDE + col;    // stage h'
            *reinterpret_cast<float4*>(sp)     = make_float4(o[0],o[1],o[2],o[3]);
            *reinterpret_cast<float4*>(sp + 4) = make_float4(o[4],o[5],o[6],o[7]);
            float* op = hout + (size_t)n * HID + col;
            *reinterpret_cast<float4*>(op)     = make_float4(o[0],o[1],o[2],o[3]);
            *reinterpret_cast<float4*>(op + 4) = make_float4(o[4],o[5],o[6],o[7]);
        }
    }

    if (!hasNext) return;

    // ---- P = h' @ W1n + B1n (h' tile in sH, full 128x128) ----
    {
        float4 b0 = *reinterpret_cast<const float4*>(B1n + col);
        float4 b1 = *reinterpret_cast<const float4*>(B1n + col + 4);
        float bb[8] = {b0.x,b0.y,b0.z,b0.w,b1.x,b1.y,b1.z,b1.w};
        #pragma unroll
        for (int i = 0; i < 8; i++)
            #pragma unroll
            for (int j = 0; j < 8; j++) acc[i][j] = bb[j];
    }
    for (int kt = 0; kt < 8; kt++) {
        const int k0 = kt * 16;
        __syncthreads();
        #pragma unroll
        for (int q = 0; q < 2; q++) {
            int s  = t * 2 + q;
            int kr = s >> 5;
            int c  = (s & 31) * 4;
            *reinterpret_cast<float4*>(&sB[kr][c]) =
                *reinterpret_cast<const float4*>(W1n + (size_t)(k0 + kr) * HID + c);
        }
        __syncthreads();
        #pragma unroll
        for (int k = 0; k < 16; k++) {
            float a[8];
            #pragma unroll
            for (int i = 0; i < 8; i++) a[i] = sH[(ty*8 + i) * SH_STRIDE + k0 + k];
            float4 b0 = *reinterpret_cast<float4*>(&sB[k][col]);
            float4 b1 = *reinterpret_cast<float4*>(&sB[k][col + 4]);
            float bb[8] = {b0.x,b0.y,b0.z,b0.w,b1.x,b1.y,b1.z,b1.w};
            #pragma unroll
            for (int i = 0; i < 8; i++)
                #pragma unroll
                for (int j = 0; j < 8; j++)
                    acc[i][j] = fmaf(a[i], bb[j], acc[i][j]);
        }
    }
    #pragma unroll
    for (int i = 0; i < 8; i++) {
        int n = n0 + ty * 8 + i;
        if (n < N_NODES) {
            float* op = g_P + (size_t)n * HID + col;
            *reinterpret_cast<float4*>(op)     = make_float4(acc[i][0],acc[i][1],acc[i][2],acc[i][3]);
            *reinterpret_cast<float4*>(op + 4) = make_float4(acc[i][4],acc[i][5],acc[i][6],acc[i][7]);
        }
    }
}

// ================= pooling / readout =================
__global__ void pool_init_kernel() {
    int i = blockIdx.x * 256 + threadIdx.x;
    g_mean[i] = 0.f;
    g_maxe[i] = ENC_NEG_INF;
    if (i < NGRAPHS) g_cnt[i] = 0.f;
}

__global__ void pool_acc_kernel(int ping, const int* __restrict__ batch) {
    int idx = blockIdx.x * 256 + threadIdx.x;
    int n = idx >> 7, c = idx & 127;
    float v = g_h[ping][idx];
    int gph = batch[n];
    atomicAdd(&g_mean[gph * HID + c], v);
    atomicMax(&g_maxe[gph * HID + c], fenc(v));
    if (c == 0) atomicAdd(&g_cnt[gph], 1.f);
}

__global__ void readout_kernel(const float* __restrict__ W1,
                               const float* __restrict__ B1,
                               const float* __restrict__ W2,
                               const float* __restrict__ B2,
                               float* __restrict__ out)
{
    __shared__ float gv[256];
    __shared__ float red[128];
    const int g = blockIdx.x, t = threadIdx.x;
    float cnt = fmaxf(g_cnt[g], 1.f);
    gv[t]       = g_mean[g * HID + t] / cnt;
    gv[128 + t] = fdec(g_maxe[g * HID + t]);
    __syncthreads();
    float a = B1[t];
    #pragma unroll 8
    for (int k = 0; k < 256; k++)
        a = fmaf(gv[k], W1[(size_t)k * HID + t], a);
    a = fmaxf(a, 0.f) * W2[t];
    red[t] = a;
    __syncthreads();
    for (int s2 = 64; s2 > 0; s2 >>= 1) {
        if (t < s2) red[t] += red[t + s2];
        __syncthreads();
    }
    if (t == 0) out[g] = red[0] + B2[0];
}

// ================= launch =================
extern "C" void kernel_launch(void* const* d_in, const int* in_sizes, int n_in,
                              void* d_out, int out_size)
{
    const float* x     = (const float*)d_in[0];
    const int*   ei    = (const int*)  d_in[1];
    const float* eattr = (const float*)d_in[2];
    const int*   batch = (const int*)  d_in[3];
    const float* npw   = (const float*)d_in[4];
    const float* npb   = (const float*)d_in[5];
    const float* mw1   = (const float*)d_in[6];
    const float* mb1   = (const float*)d_in[7];
    const float* mw2   = (const float*)d_in[8];
    const float* mb2   = (const float*)d_in[9];
    const float* uw    = (const float*)d_in[10];
    const float* ub    = (const float*)d_in[11];
    const float* lg    = (const float*)d_in[12];
    const float* lb    = (const float*)d_in[13];
    const float* fw1   = (const float*)d_in[14];
    const float* fb1   = (const float*)d_in[15];
    const float* fw2   = (const float*)d_in[16];
    const float* fb2   = (const float*)d_in[17];
    float* out = (float*)d_out;

    const int* srcIdx = ei;
    const int* dstIdx = ei + N_EDGES;

    cudaFuncSetAttribute(update_kernel,
                         cudaFuncAttributeMaxDynamicSharedMemorySize,
                         UPD_SMEM_BYTES);

    node_proj_kernel<<<N_NODES / 16, 256>>>(x, npw, npb);
    deg_zero_kernel<<<(N_NODES + 255) / 256, 256>>>();
    deg_count_kernel<<<N_EDGES / 256, 256>>>(dstIdx);

    // P for layer 0
    pre_kernel<<<(N_NODES + 127) / 128, 256>>>(0, mw1, mb1);

    int ping = 0;
    for (int l = 0; l < NLAYERS; l++) {
        const float* W1l   = mw1 + (size_t)l * (HID + EDGE_DIM) * HID;
        const float* W1el  = W1l + (size_t)HID * HID;
        const float* W2l   = mw2 + (size_t)l * HID * HID;
        const float* Wul   = uw  + (size_t)l * 2 * HID * HID;
        const float* WuBot = Wul + (size_t)HID * HID;
        const int hasNext  = (l + 1 < NLAYERS);
        const float* W1n   = hasNext ? (W1l + (size_t)(HID + EDGE_DIM) * HID) : W1l;
        const float* B1n   = hasNext ? (mb1 + (size_t)(l + 1) * HID) : mb1;

        zero_R_kernel<<<(N_NODES * HID / 4) / 256, 256>>>();
        compose_kernel<<<64, 256>>>(W2l, WuBot, mb2 + (size_t)l * HID);
        edge_kernel<<<N_ETILES, 256>>>(eattr, srcIdx, dstIdx, W1el);
        update_kernel<<<(N_NODES + 127) / 128, 256, UPD_SMEM_BYTES>>>(
            ping, Wul, ub + (size_t)l * HID,
            lg + (size_t)l * HID, lb + (size_t)l * HID,
            W1n, B1n, hasNext);
        ping ^= 1;
    }

    pool_init_kernel<<<(NGRAPHS * HID) / 256, 256>>>();
    pool_acc_kernel<<<(N_NODES * HID) / 256, 256>>>(ping, batch);
    readout_kernel<<<NGRAPHS, 128>>>(fw1, fb1, fw2, fb2, out);
}

// round 7
// speedup vs baseline: 5.2779x; 1.0083x over previous
#include <cuda_runtime.h>
#include <cuda_bf16.h>
#include <cstdint>
#include <math.h>

#define N_NODES   20000
#define N_EDGES   640000
#define IN_CH     64
#define EDGE_DIM  16
#define HID       128
#define NLAYERS   3
#define NGRAPHS   128
#define ETILE     128
#define N_ETILES  (N_EDGES / ETILE)   // 5000

// ================= scratch (device globals) =================
__device__ float     g_h[2][N_NODES * HID];
__device__ float     g_P[N_NODES * HID];
__device__ float     g_R[N_NODES * HID];
__device__ float     g_wcomp[NLAYERS][HID * HID];   // W2 @ Wu_bot
__device__ float     g_bvec[NLAYERS][HID];          // b2 @ Wu_bot
__device__ float     g_deg[N_NODES];
__device__ float     g_mean[NGRAPHS * HID];
__device__ unsigned  g_maxe[NGRAPHS * HID];
__device__ float     g_cnt[NGRAPHS];

__device__ __forceinline__ unsigned fenc(float f) {
    unsigned u = __float_as_uint(f);
    return (u & 0x80000000u) ? ~u : (u | 0x80000000u);
}
__device__ __forceinline__ float fdec(unsigned u) {
    return (u & 0x80000000u) ? __uint_as_float(u & 0x7FFFFFFFu)
                             : __uint_as_float(~u);
}
#define ENC_NEG_INF 0x007FFFFFu

// ================= node projection: h0 = x @ W + b =================
__global__ void node_proj_kernel(const float* __restrict__ x,
                                 const float* __restrict__ W,
                                 const float* __restrict__ B) {
    __shared__ float sX[16][IN_CH];
    const int t  = threadIdx.x;
    const int n0 = blockIdx.x * 16;
    for (int i = t; i < 16 * IN_CH; i += 256) {
        int r = i >> 6, c = i & 63;
        sX[r][c] = x[(size_t)(n0 + r) * IN_CH + c];
    }
    __syncthreads();
    const int row = t >> 4;
    const int col = (t & 15) * 8;
    float acc[8];
    {
        float4 b0 = *reinterpret_cast<const float4*>(B + col);
        float4 b1 = *reinterpret_cast<const float4*>(B + col + 4);
        acc[0]=b0.x; acc[1]=b0.y; acc[2]=b0.z; acc[3]=b0.w;
        acc[4]=b1.x; acc[5]=b1.y; acc[6]=b1.z; acc[7]=b1.w;
    }
    #pragma unroll 8
    for (int k = 0; k < IN_CH; k++) {
        float a = sX[row][k];
        float4 w0 = *reinterpret_cast<const float4*>(W + (size_t)k * HID + col);
        float4 w1 = *reinterpret_cast<const float4*>(W + (size_t)k * HID + col + 4);
        acc[0] = fmaf(a, w0.x, acc[0]); acc[1] = fmaf(a, w0.y, acc[1]);
        acc[2] = fmaf(a, w0.z, acc[2]); acc[3] = fmaf(a, w0.w, acc[3]);
        acc[4] = fmaf(a, w1.x, acc[4]); acc[5] = fmaf(a, w1.y, acc[5]);
        acc[6] = fmaf(a, w1.z, acc[6]); acc[7] = fmaf(a, w1.w, acc[7]);
    }
    float* out = g_h[0] + (size_t)(n0 + row) * HID + col;
    *reinterpret_cast<float4*>(out)     = make_float4(acc[0], acc[1], acc[2], acc[3]);
    *reinterpret_cast<float4*>(out + 4) = make_float4(acc[4], acc[5], acc[6], acc[7]);
}

// ======= init: deg=0, pool accumulators reset (once per run) =======
__global__ void init_kernel() {
    int i = blockIdx.x * 256 + threadIdx.x;   // 80 blocks x 256 = 20480
    if (i < N_NODES) g_deg[i] = 0.f;
    if (i < NGRAPHS * HID) { g_mean[i] = 0.f; g_maxe[i] = ENC_NEG_INF; }
    if (i < NGRAPHS) g_cnt[i] = 0.f;
}
__global__ void deg_count_kernel(const int* __restrict__ dstIdx) {
    int i = blockIdx.x * 256 + threadIdx.x;
    atomicAdd(&g_deg[dstIdx[i]], 1.f);
}
__global__ void cnt_count_kernel(const int* __restrict__ batch) {
    int i = blockIdx.x * 256 + threadIdx.x;
    if (i < N_NODES) atomicAdd(&g_cnt[batch[i]], 1.f);
}
__global__ void zero_R_kernel() {
    int i = blockIdx.x * 256 + threadIdx.x;
    reinterpret_cast<float4*>(g_R)[i] = make_float4(0.f, 0.f, 0.f, 0.f);
}

// ===== compose (all layers, once): wcomp[l] = W2[l]@WuBot[l]; bvec likewise
__global__ void compose_kernel(const float* __restrict__ mw2,
                               const float* __restrict__ uw,
                               const float* __restrict__ mb2)
{
    const int l   = blockIdx.y;
    const float* W2    = mw2 + (size_t)l * HID * HID;
    const float* WuBot = uw  + (size_t)l * 2 * HID * HID + (size_t)HID * HID;
    const float* b2    = mb2 + (size_t)l * HID;
    int idx = blockIdx.x * 256 + threadIdx.x;   // 64 x 256 = 16384
    int j   = idx >> 7;
    int out = idx & 127;
    float acc = 0.f;
    #pragma unroll 8
    for (int c = 0; c < HID; c++)
        acc = fmaf(W2[(size_t)j * HID + c], WuBot[(size_t)c * HID + out], acc);
    g_wcomp[l][(size_t)j * HID + out] = acc;
    if (idx < HID) {
        float bv = 0.f;
        #pragma unroll 8
        for (int c = 0; c < HID; c++)
            bv = fmaf(b2[c], WuBot[(size_t)c * HID + out], bv);
        g_bvec[l][out] = bv;
    }
}

// ================= pre (layer 0 only): P = h0 @ W1[:128] + b1 =========
__global__ void __launch_bounds__(256, 1) pre_kernel(
    const float* __restrict__ W, const float* __restrict__ B)
{
    __shared__ float sA[128][17];
    __shared__ float sB[16][128];
    const float* __restrict__ h = g_h[0];
    const int t  = threadIdx.x;
    const int n0 = blockIdx.x * 128;
    const int tx = t & 15;
    const int ty = t >> 4;
    const int col = tx * 8;

    float acc[8][8];
    {
        float4 b0 = *reinterpret_cast<const float4*>(B + col);
        float4 b1 = *reinterpret_cast<const float4*>(B + col + 4);
        float bb[8] = {b0.x,b0.y,b0.z,b0.w,b1.x,b1.y,b1.z,b1.w};
        #pragma unroll
        for (int i = 0; i < 8; i++)
            #pragma unroll
            for (int j = 0; j < 8; j++) acc[i][j] = bb[j];
    }

    for (int kt = 0; kt < 8; kt++) {
        const int k0 = kt * 16;
        __syncthreads();
        #pragma unroll
        for (int q = 0; q < 2; q++) {
            int s = t * 2 + q;
            int r = s >> 2;
            int c = (s & 3) * 4;
            int n = n0 + r;
            if (n >= N_NODES) n = 0;
            float4 v = *reinterpret_cast<const float4*>(h + (size_t)n * HID + k0 + c);
            sA[r][c] = v.x; sA[r][c+1] = v.y; sA[r][c+2] = v.z; sA[r][c+3] = v.w;
        }
        #pragma unroll
        for (int q = 0; q < 2; q++) {
            int s  = t * 2 + q;
            int kr = s >> 5;
            int c  = (s & 31) * 4;
            *reinterpret_cast<float4*>(&sB[kr][c]) =
                *reinterpret_cast<const float4*>(W + (size_t)(k0 + kr) * HID + c);
        }
        __syncthreads();
        #pragma unroll
        for (int k = 0; k < 16; k++) {
            float a[8];
            #pragma unroll
            for (int i = 0; i < 8; i++) a[i] = sA[ty*8 + i][k];
            float4 b0 = *reinterpret_cast<float4*>(&sB[k][col]);
            float4 b1 = *reinterpret_cast<float4*>(&sB[k][col + 4]);
            float bb[8] = {b0.x,b0.y,b0.z,b0.w,b1.x,b1.y,b1.z,b1.w};
            #pragma unroll
            for (int i = 0; i < 8; i++)
                #pragma unroll
                for (int j = 0; j < 8; j++)
                    acc[i][j] = fmaf(a[i], bb[j], acc[i][j]);
        }
    }

    #pragma unroll
    for (int i = 0; i < 8; i++) {
        int n = n0 + ty * 8 + i;
        if (n < N_NODES) {
            float* op = g_P + (size_t)n * HID + col;
            *reinterpret_cast<float4*>(op)     = make_float4(acc[i][0],acc[i][1],acc[i][2],acc[i][3]);
            *reinterpret_cast<float4*>(op + 4) = make_float4(acc[i][4],acc[i][5],acc[i][6],acc[i][7]);
        }
    }
}

// ================= edge kernel: R[dst] += relu(P[src] + ea @ W1e) =========
// 4 edges in flight per warp per pass (MLP=4 gather)
__global__ void __launch_bounds__(256) edge_kernel(
    const float* __restrict__ eattr,
    const int*   __restrict__ srcIdx,
    const int*   __restrict__ dstIdx,
    const float* __restrict__ W1e)
{
    __shared__ float sEA[ETILE][EDGE_DIM];
    __shared__ int sSrc[ETILE], sDst[ETILE];
    const int t    = threadIdx.x;
    const int lane = t & 31;
    const int warp = t >> 5;
    const int e0   = blockIdx.x * ETILE;

    if (t < ETILE) { sSrc[t] = srcIdx[e0 + t]; sDst[t] = dstIdx[e0 + t]; }

    {
        const float4* ea4 = reinterpret_cast<const float4*>(
            eattr + (size_t)e0 * EDGE_DIM);
        float4* s4 = reinterpret_cast<float4*>(&sEA[0][0]);
        s4[t]       = ea4[t];
        s4[t + 256] = ea4[t + 256];
    }

    float4 w[16];
    #pragma unroll
    for (int k = 0; k < 16; k++)
        w[k] = *reinterpret_cast<const float4*>(W1e + (size_t)k * HID + lane * 4);
    __syncthreads();

    const int ebase = warp * 16;
    #pragma unroll
    for (int grp = 0; grp < 4; grp++) {
        int e[4];
        float4 p[4];
        #pragma unroll
        for (int q = 0; q < 4; q++) {
            e[q] = ebase + grp * 4 + q;
            p[q] = *reinterpret_cast<const float4*>(
                g_P + (size_t)sSrc[e[q]] * HID + lane * 4);
        }
        float ac[4][4];
        #pragma unroll
        for (int q = 0; q < 4; q++) {
            ac[q][0] = p[q].x; ac[q][1] = p[q].y;
            ac[q][2] = p[q].z; ac[q][3] = p[q].w;
        }
        #pragma unroll
        for (int k = 0; k < 16; k++) {
            float4 wk = w[k];
            #pragma unroll
            for (int q = 0; q < 4; q++) {
                float a = sEA[e[q]][k];
                ac[q][0] = fmaf(a, wk.x, ac[q][0]);
                ac[q][1] = fmaf(a, wk.y, ac[q][1]);
                ac[q][2] = fmaf(a, wk.z, ac[q][2]);
                ac[q][3] = fmaf(a, wk.w, ac[q][3]);
            }
        }
        #pragma unroll
        for (int q = 0; q < 4; q++) {
            float r0 = fmaxf(ac[q][0], 0.f), r1 = fmaxf(ac[q][1], 0.f);
            float r2 = fmaxf(ac[q][2], 0.f), r3 = fmaxf(ac[q][3], 0.f);
            float* rp = g_R + (size_t)sDst[e[q]] * HID + lane * 4;
            asm volatile("red.global.add.v4.f32 [%0], {%1,%2,%3,%4};"
                         :: "l"(rp), "f"(r0), "f"(r1), "f"(r2), "f"(r3)
                         : "memory");
        }
    }
}

// ====== fused update ======
// h' = relu(LN(relu([h,R]@Wu + deg*bvec + b))) + h
// hasNext: stage h' -> SMEM, P = h'@W1n + B1n; write h'
// !hasNext: pool (mean/max atomics) directly; skip h' write
// always: zero own R rows for next layer
#define SH_STRIDE 132
#define UPD_OFF_SA   0                              // 128*17*4   = 8704
#define UPD_OFF_SB   8704                           // 16*128*4   = 8192
#define UPD_OFF_SH   16896                          // 128*132*4  = 67584
#define UPD_OFF_DEG  84480                          // 128*4
#define UPD_SMEM_BYTES 84992

__global__ void __launch_bounds__(256, 1) update_kernel(
    int ping, int layer,
    const float* __restrict__ Wtop,
    const float* __restrict__ B,
    const float* __restrict__ LG,
    const float* __restrict__ LB,
    const float* __restrict__ W1n,
    const float* __restrict__ B1n,
    const int*   __restrict__ batch,
    int hasNext)
{
    extern __shared__ char usm[];
    float (*sA)[17]  = (float(*)[17])(usm + UPD_OFF_SA);
    float (*sB)[128] = (float(*)[128])(usm + UPD_OFF_SB);
    float* sH        = (float*)(usm + UPD_OFF_SH);
    float* sDeg      = (float*)(usm + UPD_OFF_DEG);

    const float* __restrict__ h    = g_h[ping];
    float*       __restrict__ hout = g_h[ping ^ 1];
    const float* __restrict__ wcomp = g_wcomp[layer];
    const int t  = threadIdx.x;
    const int n0 = blockIdx.x * 128;
    const int tx = t & 15;
    const int ty = t >> 4;
    const int col = tx * 8;

    if (t < 128) {
        int n = n0 + t;
        sDeg[t] = (n < N_NODES) ? g_deg[n] : 0.f;
    }

    float acc[8][8];
    {
        float4 b0 = *reinterpret_cast<const float4*>(B + col);
        float4 b1 = *reinterpret_cast<const float4*>(B + col + 4);
        float bb[8] = {b0.x,b0.y,b0.z,b0.w,b1.x,b1.y,b1.z,b1.w};
        #pragma unroll
        for (int i = 0; i < 8; i++)
            #pragma unroll
            for (int j = 0; j < 8; j++) acc[i][j] = bb[j];
    }

    for (int kt = 0; kt < 16; kt++) {
        const int k0 = kt * 16;
        __syncthreads();
        #pragma unroll
        for (int q = 0; q < 2; q++) {
            int s = t * 2 + q;
            int r = s >> 2;
            int c = (s & 3) * 4;
            int n = n0 + r;
            if (n >= N_NODES) n = 0;
            const float* srcp = (k0 < 128)
                ? (h   + (size_t)n * HID + k0 + c)
                : (g_R + (size_t)n * HID + (k0 - 128) + c);
            float4 v = *reinterpret_cast<const float4*>(srcp);
            sA[r][c] = v.x; sA[r][c+1] = v.y; sA[r][c+2] = v.z; sA[r][c+3] = v.w;
        }
        #pragma unroll
        for (int q = 0; q < 2; q++) {
            int s  = t * 2 + q;
            int kr = s >> 5;
            int c  = (s & 31) * 4;
            const float* wp = (k0 < 128)
                ? (Wtop  + (size_t)(k0 + kr) * HID + c)
                : (wcomp + (size_t)(k0 - 128 + kr) * HID + c);
            *reinterpret_cast<float4*>(&sB[kr][c]) =
                *reinterpret_cast<const float4*>(wp);
        }
        __syncthreads();
        #pragma unroll
        for (int k = 0; k < 16; k++) {
            float a[8];
            #pragma unroll
            for (int i = 0; i < 8; i++) a[i] = sA[ty*8 + i][k];
            float4 b0 = *reinterpret_cast<float4*>(&sB[k][col]);
            float4 b1 = *reinterpret_cast<float4*>(&sB[k][col + 4]);
            float bb[8] = {b0.x,b0.y,b0.z,b0.w,b1.x,b1.y,b1.z,b1.w};
            #pragma unroll
            for (int i = 0; i < 8; i++)
                #pragma unroll
                for (int j = 0; j < 8; j++)
                    acc[i][j] = fmaf(a[i], bb[j], acc[i][j]);
        }
    }

    float4 g0  = *reinterpret_cast<const float4*>(LG + col);
    float4 g1  = *reinterpret_cast<const float4*>(LG + col + 4);
    float4 lb0 = *reinterpret_cast<const float4*>(LB + col);
    float4 lb1 = *reinterpret_cast<const float4*>(LB + col + 4);
    float4 bv0 = *reinterpret_cast<const float4*>(g_bvec[layer] + col);
    float4 bv1 = *reinterpret_cast<const float4*>(g_bvec[layer] + col + 4);
    float gg[8]  = {g0.x,g0.y,g0.z,g0.w,g1.x,g1.y,g1.z,g1.w};
    float lbv[8] = {lb0.x,lb0.y,lb0.z,lb0.w,lb1.x,lb1.y,lb1.z,lb1.w};
    float bvv[8] = {bv0.x,bv0.y,bv0.z,bv0.w,bv1.x,bv1.y,bv1.z,bv1.w};

    #pragma unroll
    for (int i = 0; i < 8; i++) {
        float dg = sDeg[ty * 8 + i];
        float s = 0.f, q = 0.f;
        #pragma unroll
        for (int j = 0; j < 8; j++) {
            acc[i][j] = fmaxf(acc[i][j] + dg * bvv[j], 0.f);
            s += acc[i][j]; q += acc[i][j] * acc[i][j];
        }
        #pragma unroll
        for (int m = 1; m < 16; m <<= 1) {
            s += __shfl_xor_sync(0xffffffffu, s, m);
            q += __shfl_xor_sync(0xffffffffu, q, m);
        }
        float mu  = s * (1.f / 128.f);
        float var = q * (1.f / 128.f) - mu * mu;
        float rs  = rsqrtf(var + 1e-5f);

        int n = n0 + ty * 8 + i;
        if (n < N_NODES) {
            const float* rp = h + (size_t)n * HID + col;
            float4 r0 = *reinterpret_cast<const float4*>(rp);
            float4 r1 = *reinterpret_cast<const float4*>(rp + 4);
            float rr[8] = {r0.x,r0.y,r0.z,r0.w,r1.x,r1.y,r1.z,r1.w};
            float o[8];
            #pragma unroll
            for (int j = 0; j < 8; j++) {
                float v = (acc[i][j] - mu) * rs * gg[j] + lbv[j];
                o[j] = fmaxf(v, 0.f) + rr[j];
            }
            if (hasNext) {
                float* sp = sH + (ty*8 + i) * SH_STRIDE + col;
                *reinterpret_cast<float4*>(sp)     = make_float4(o[0],o[1],o[2],o[3]);
                *reinterpret_cast<float4*>(sp + 4) = make_float4(o[4],o[5],o[6],o[7]);
                float* op = hout + (size_t)n * HID + col;
                *reinterpret_cast<float4*>(op)     = make_float4(o[0],o[1],o[2],o[3]);
                *reinterpret_cast<float4*>(op + 4) = make_float4(o[4],o[5],o[6],o[7]);
            } else {
                int gph = batch[n];
                #pragma unroll
                for (int j = 0; j < 8; j++) {
                    atomicAdd(&g_mean[gph * HID + col + j], o[j]);
                    atomicMax(&g_maxe[gph * HID + col + j], fenc(o[j]));
                }
            }
        }
    }

    // ---- zero own R rows for next layer (this block is R's only reader) ----
    {
        float4 z = make_float4(0.f, 0.f, 0.f, 0.f);
        #pragma unroll
        for (int q = 0; q < 16; q++) {
            int idx = q * 256 + t;              // 4096 float4 = 128 rows
            int n = n0 + (idx >> 5);
            if (n < N_NODES)
                reinterpret_cast<float4*>(g_R + (size_t)n * HID)[idx & 31] = z;
        }
    }

    if (!hasNext) return;

    // ---- P = h' @ W1n + B1n (h' tile in sH) ----
    {
        float4 b0 = *reinterpret_cast<const float4*>(B1n + col);
        float4 b1 = *reinterpret_cast<const float4*>(B1n + col + 4);
        float bb[8] = {b0.x,b0.y,b0.z,b0.w,b1.x,b1.y,b1.z,b1.w};
        #pragma unroll
        for (int i = 0; i < 8; i++)
            #pragma unroll
            for (int j = 0; j < 8; j++) acc[i][j] = bb[j];
    }
    for (int kt = 0; kt < 8; kt++) {
        const int k0 = kt * 16;
        __syncthreads();
        #pragma unroll
        for (int q = 0; q < 2; q++) {
            int s  = t * 2 + q;
            int kr = s >> 5;
            int c  = (s & 31) * 4;
            *reinterpret_cast<float4*>(&sB[kr][c]) =
                *reinterpret_cast<const float4*>(W1n + (size_t)(k0 + kr) * HID + c);
        }
        __syncthreads();
        #pragma unroll
        for (int k = 0; k < 16; k++) {
            float a[8];
            #pragma unroll
            for (int i = 0; i < 8; i++) a[i] = sH[(ty*8 + i) * SH_STRIDE + k0 + k];
            float4 b0 = *reinterpret_cast<float4*>(&sB[k][col]);
            float4 b1 = *reinterpret_cast<float4*>(&sB[k][col + 4]);
            float bb[8] = {b0.x,b0.y,b0.z,b0.w,b1.x,b1.y,b1.z,b1.w};
            #pragma unroll
            for (int i = 0; i < 8; i++)
                #pragma unroll
                for (int j = 0; j < 8; j++)
                    acc[i][j] = fmaf(a[i], bb[j], acc[i][j]);
        }
    }
    #pragma unroll
    for (int i = 0; i < 8; i++) {
        int n = n0 + ty * 8 + i;
        if (n < N_NODES) {
            float* op = g_P + (size_t)n * HID + col;
            *reinterpret_cast<float4*>(op)     = make_float4(acc[i][0],acc[i][1],acc[i][2],acc[i][3]);
            *reinterpret_cast<float4*>(op + 4) = make_float4(acc[i][4],acc[i][5],acc[i][6],acc[i][7]);
        }
    }
}

// ================= readout =================
__global__ void readout_kernel(const float* __restrict__ W1,
                               const float* __restrict__ B1,
                               const float* __restrict__ W2,
                               const float* __restrict__ B2,
                               float* __restrict__ out)
{
    __shared__ float gv[256];
    __shared__ float red[128];
    const int g = blockIdx.x, t = threadIdx.x;
    float cnt = fmaxf(g_cnt[g], 1.f);
    gv[t]       = g_mean[g * HID + t] / cnt;
    gv[128 + t] = fdec(g_maxe[g * HID + t]);
    __syncthreads();
    float a = B1[t];
    #pragma unroll 8
    for (int k = 0; k < 256; k++)
        a = fmaf(gv[k], W1[(size_t)k * HID + t], a);
    a = fmaxf(a, 0.f) * W2[t];
    red[t] = a;
    __syncthreads();
    for (int s2 = 64; s2 > 0; s2 >>= 1) {
        if (t < s2) red[t] += red[t + s2];
        __syncthreads();
    }
    if (t == 0) out[g] = red[0] + B2[0];
}

// ================= launch =================
extern "C" void kernel_launch(void* const* d_in, const int* in_sizes, int n_in,
                              void* d_out, int out_size)
{
    const float* x     = (const float*)d_in[0];
    const int*   ei    = (const int*)  d_in[1];
    const float* eattr = (const float*)d_in[2];
    const int*   batch = (const int*)  d_in[3];
    const float* npw   = (const float*)d_in[4];
    const float* npb   = (const float*)d_in[5];
    const float* mw1   = (const float*)d_in[6];
    const float* mb1   = (const float*)d_in[7];
    const float* mw2   = (const float*)d_in[8];
    const float* mb2   = (const float*)d_in[9];
    const float* uw    = (const float*)d_in[10];
    const float* ub    = (const float*)d_in[11];
    const float* lg    = (const float*)d_in[12];
    const float* lb    = (const float*)d_in[13];
    const float* fw1   = (const float*)d_in[14];
    const float* fb1   = (const float*)d_in[15];
    const float* fw2   = (const float*)d_in[16];
    const float* fb2   = (const float*)d_in[17];
    float* out = (float*)d_out;

    const int* srcIdx = ei;
    const int* dstIdx = ei + N_EDGES;

    cudaFuncSetAttribute(update_kernel,
                         cudaFuncAttributeMaxDynamicSharedMemorySize,
                         UPD_SMEM_BYTES);

    node_proj_kernel<<<N_NODES / 16, 256>>>(x, npw, npb);
    init_kernel<<<80, 256>>>();
    deg_count_kernel<<<N_EDGES / 256, 256>>>(dstIdx);
    cnt_count_kernel<<<(N_NODES + 255) / 256, 256>>>(batch);
    {
        dim3 cg(64, NLAYERS);
        compose_kernel<<<cg, 256>>>(mw2, uw, mb2);
    }
    zero_R_kernel<<<(N_NODES * HID / 4) / 256, 256>>>();
    pre_kernel<<<(N_NODES + 127) / 128, 256>>>(mw1, mb1);

    int ping = 0;
    for (int l = 0; l < NLAYERS; l++) {
        const float* W1l  = mw1 + (size_t)l * (HID + EDGE_DIM) * HID;
        const float* W1el = W1l + (size_t)HID * HID;
        const float* Wul  = uw  + (size_t)l * 2 * HID * HID;
        const int hasNext = (l + 1 < NLAYERS);
        const float* W1n  = hasNext ? (W1l + (size_t)(HID + EDGE_DIM) * HID) : W1l;
        const float* B1n  = hasNext ? (mb1 + (size_t)(l + 1) * HID) : mb1;

        edge_kernel<<<N_ETILES, 256>>>(eattr, srcIdx, dstIdx, W1el);
        update_kernel<<<(N_NODES + 127) / 128, 256, UPD_SMEM_BYTES>>>(
            ping, l, Wul, ub + (size_t)l * HID,
            lg + (size_t)l * HID, lb + (size_t)l * HID,
            W1n, B1n, batch, hasNext);
        ping ^= 1;
    }

    readout_kernel<<<NGRAPHS, 128>>>(fw1, fb1, fw2, fb2, out);
}